// round 2
// baseline (speedup 1.0000x reference)
#include <cuda_runtime.h>
#include <cuda_bf16.h>
#include <stdint.h>

// ---------------------------------------------------------------------------
// GCN 2-layer:  out = Anorm @ relu(Anorm @ (x@W1) + b1) @ W2 + b2
// Layer 2 uses linearity: (Anorm @ h1relu) @ W2 + b2, so both aggregations
// run over 400 features.
// ---------------------------------------------------------------------------

#define N_NODES 50000
#define MAX_E   1600000
#define MAX_CSR (MAX_E + N_NODES)
#define F_HID   400

// scratch (no runtime allocation allowed)
__device__ float g_h1[(size_t)N_NODES * F_HID];    // x@W1, later reused for agg2
__device__ float g_agg1[(size_t)N_NODES * F_HID];  // relu(agg(h1)+b1)
__device__ float g_dinv[N_NODES];
__device__ int   g_deg[N_NODES];
__device__ int   g_fill[N_NODES];
__device__ int   g_rowptr[N_NODES + 1];
__device__ int   g_csr[MAX_CSR];
__device__ int   g_bsums[512];
__device__ int   g_is64;

// ---------------------------------------------------------------------------
// edge dtype detection: harness may deliver edge_index as int32 or int64.
// If int32, interpreting pairs as int64 gives values >= 2^32 (hi word is a
// random node id, ~never 0 sixteen times in a row).
// ---------------------------------------------------------------------------
__global__ void k_detect(const void* __restrict__ ei) {
    if (threadIdx.x == 0 && blockIdx.x == 0) {
        const long long* p = (const long long*)ei;
        int ok64 = 1;
#pragma unroll
        for (int i = 0; i < 16; i++) {
            long long v = p[i];
            if (v < 0 || v >= N_NODES) ok64 = 0;
        }
        g_is64 = ok64;
    }
}

__device__ __forceinline__ int edge_at(const void* ei, size_t idx) {
    if (g_is64) return (int)((const long long*)ei)[idx];
    return ((const int*)ei)[idx];
}

// ---------------------------------------------------------------------------
// degree / dinv
// ---------------------------------------------------------------------------
__global__ void k_init(int n) {
    int i = blockIdx.x * blockDim.x + threadIdx.x;
    if (i < n) { g_deg[i] = 1; g_fill[i] = 0; }   // deg starts at 1 (self loop)
}

__global__ void k_count_deg(const void* __restrict__ ei, int E) {
    int i = blockIdx.x * blockDim.x + threadIdx.x;
    if (i < E) {
        int d = edge_at(ei, (size_t)E + i);
        if ((unsigned)d < (unsigned)N_NODES) atomicAdd(&g_deg[d], 1);
    }
}

__global__ void k_dinv(int n) {
    int i = blockIdx.x * blockDim.x + threadIdx.x;
    if (i < n) g_dinv[i] = rsqrtf((float)g_deg[i]);
}

// ---------------------------------------------------------------------------
// exclusive scan of g_deg -> g_rowptr  (3-kernel scheme, n = 50000)
// ---------------------------------------------------------------------------
__device__ __forceinline__ int warp_incl_scan(int v) {
#pragma unroll
    for (int o = 1; o < 32; o <<= 1) {
        int t = __shfl_up_sync(0xffffffffu, v, o);
        if ((threadIdx.x & 31) >= o) v += t;
    }
    return v;
}

__global__ void k_scan_blocks(const int* __restrict__ in, int* __restrict__ out,
                              int* __restrict__ bsums, int n) {
    __shared__ int wsum[8];
    int i = blockIdx.x * 256 + threadIdx.x;
    int v = (i < n) ? in[i] : 0;
    int inc = warp_incl_scan(v);
    int lane = threadIdx.x & 31, w = threadIdx.x >> 5;
    if (lane == 31) wsum[w] = inc;
    __syncthreads();
    if (w == 0) {
        int s = (lane < 8) ? wsum[lane] : 0;
        s = warp_incl_scan(s);
        if (lane < 8) wsum[lane] = s;
    }
    __syncthreads();
    int off = (w > 0) ? wsum[w - 1] : 0;
    if (i < n) out[i] = off + inc - v;            // exclusive within block
    if (threadIdx.x == 255) bsums[blockIdx.x] = off + inc;  // block total
}

__global__ void k_scan_sums(int* __restrict__ bsums, int nb, int* __restrict__ total_out) {
    __shared__ int wsum[8];
    int v = (threadIdx.x < nb) ? bsums[threadIdx.x] : 0;
    int inc = warp_incl_scan(v);
    int lane = threadIdx.x & 31, w = threadIdx.x >> 5;
    if (lane == 31) wsum[w] = inc;
    __syncthreads();
    if (w == 0) {
        int s = (lane < 8) ? wsum[lane] : 0;
        s = warp_incl_scan(s);
        if (lane < 8) wsum[lane] = s;
    }
    __syncthreads();
    int off = (w > 0) ? wsum[w - 1] : 0;
    if (threadIdx.x < nb) bsums[threadIdx.x] = off + inc - v;  // exclusive
    if (threadIdx.x == 255) *total_out = off + inc;            // grand total
}

__global__ void k_scan_add(int* __restrict__ out, const int* __restrict__ bsums, int n) {
    int i = blockIdx.x * 256 + threadIdx.x;
    if (i < n) out[i] += bsums[blockIdx.x];
}

// ---------------------------------------------------------------------------
// CSR fill:  edges + self loops
// ---------------------------------------------------------------------------
__global__ void k_fill_csr(const void* __restrict__ ei, int E, int n) {
    int i = blockIdx.x * blockDim.x + threadIdx.x;
    int total = E + n;
    if (i >= total) return;
    int s, d;
    if (i < E) {
        s = edge_at(ei, i);
        d = edge_at(ei, (size_t)E + i);
        if ((unsigned)s >= (unsigned)n || (unsigned)d >= (unsigned)n) return;
    } else {
        s = d = i - E;
    }
    int pos = atomicAdd(&g_fill[d], 1);
    g_csr[g_rowptr[d] + pos] = s;
}

// ---------------------------------------------------------------------------
// SGEMM  C[M,N] = A[M,K] * B[K,N] (+bias)   128x64 tile, BK=16, 8x4/thread
// ---------------------------------------------------------------------------
template <bool BIAS>
__global__ __launch_bounds__(256) void k_sgemm(
    const float* __restrict__ A, const float* __restrict__ B,
    const float* __restrict__ bias, float* __restrict__ C,
    int M, int N, int K) {
    const int BM = 128, BN = 64, BK = 16, TM = 8, TN = 4;
    __shared__ float As[BK][BM + 4];
    __shared__ float Bs[BK][BN];

    int tid = threadIdx.x;
    int bm = blockIdx.y * BM, bn = blockIdx.x * BN;
    int ty = tid / (BN / TN);   // 0..15
    int tx = tid % (BN / TN);   // 0..15

    float acc[TM][TN];
#pragma unroll
    for (int i = 0; i < TM; i++)
#pragma unroll
        for (int j = 0; j < TN; j++) acc[i][j] = 0.f;

    for (int k0 = 0; k0 < K; k0 += BK) {
#pragma unroll
        for (int i = 0; i < (BM * BK) / 256; i++) {      // 8 elems / thread
            int idx = tid + i * 256;
            int r = idx / BK, c = idx % BK;
            int gm = bm + r, gk = k0 + c;
            As[c][r] = (gm < M && gk < K) ? A[(size_t)gm * K + gk] : 0.f;
        }
#pragma unroll
        for (int i = 0; i < (BK * BN) / 256; i++) {      // 4 elems / thread
            int idx = tid + i * 256;
            int r = idx / BN, c = idx % BN;
            int gk = k0 + r, gn = bn + c;
            Bs[r][c] = (gk < K && gn < N) ? B[(size_t)gk * N + gn] : 0.f;
        }
        __syncthreads();
#pragma unroll
        for (int k = 0; k < BK; k++) {
            float a[TM], b[TN];
            float4 a0 = *reinterpret_cast<const float4*>(&As[k][ty * TM]);
            float4 a1 = *reinterpret_cast<const float4*>(&As[k][ty * TM + 4]);
            a[0] = a0.x; a[1] = a0.y; a[2] = a0.z; a[3] = a0.w;
            a[4] = a1.x; a[5] = a1.y; a[6] = a1.z; a[7] = a1.w;
            float4 b0 = *reinterpret_cast<const float4*>(&Bs[k][tx * TN]);
            b[0] = b0.x; b[1] = b0.y; b[2] = b0.z; b[3] = b0.w;
#pragma unroll
            for (int i = 0; i < TM; i++)
#pragma unroll
                for (int j = 0; j < TN; j++) acc[i][j] += a[i] * b[j];
        }
        __syncthreads();
    }

#pragma unroll
    for (int i = 0; i < TM; i++) {
        int gm = bm + ty * TM + i;
        if (gm >= M) continue;
#pragma unroll
        for (int j = 0; j < TN; j++) {
            int gn = bn + tx * TN + j;
            if (gn >= N) continue;
            float v = acc[i][j];
            if (BIAS) v += bias[gn];
            C[(size_t)gm * N + gn] = v;
        }
    }
}

// ---------------------------------------------------------------------------
// CSR aggregation over F=400 features, one block (128 thr) per node.
// out[d][f] = sum_{s in nbrs(d)} H[s][f] * dinv[s]*dinv[d]  (+bias, relu)
// ---------------------------------------------------------------------------
template <bool RELU>
__global__ __launch_bounds__(128) void k_aggregate(
    const float* __restrict__ H, const float* __restrict__ bias,
    float* __restrict__ out, int F) {
    __shared__ int   s_idx[128];
    __shared__ float s_w[128];

    int node = blockIdx.x;
    int tid = threadIdx.x;
    int start = g_rowptr[node], end = g_rowptr[node + 1];
    float dd = g_dinv[node];

    float acc[4] = {0.f, 0.f, 0.f, 0.f};

    for (int base = start; base < end; base += 128) {
        int cnt = min(128, end - base);
        if (tid < cnt) {
            int s = g_csr[base + tid];
            s_idx[tid] = s;
            s_w[tid] = g_dinv[s] * dd;
        }
        __syncthreads();
        for (int j = 0; j < cnt; j++) {
            const float* hr = H + (size_t)s_idx[j] * F;
            float w = s_w[j];
#pragma unroll
            for (int k = 0; k < 4; k++) {
                int f = tid + k * 128;
                if (f < F) acc[k] += hr[f] * w;   // F=400: k=3 active for tid<16
            }
        }
        __syncthreads();
    }

#pragma unroll
    for (int k = 0; k < 4; k++) {
        int f = tid + k * 128;
        if (f < F) {
            float v = acc[k];
            if (bias) v += bias[f];
            if (RELU) v = fmaxf(v, 0.f);
            out[(size_t)node * F + f] = v;
        }
    }
}

// ---------------------------------------------------------------------------
// launch
// ---------------------------------------------------------------------------
extern "C" void kernel_launch(void* const* d_in, const int* in_sizes, int n_in,
                              void* d_out, int out_size) {
    const float* x  = (const float*)d_in[0];
    const void*  ei = d_in[1];
    const float* W1 = (const float*)d_in[2];
    const float* b1 = (const float*)d_in[3];
    const float* W2 = (const float*)d_in[4];
    const float* b2 = (const float*)d_in[5];
    float* out = (float*)d_out;

    const int N = N_NODES;
    const int E = in_sizes[1] / 2;
    const int IN_CH = in_sizes[2] / F_HID;           // 512
    const int H2 = in_sizes[5];                       // 800

    float *h1, *agg1;
    int *deg, *rowptr, *bsums;
    cudaGetSymbolAddress((void**)&h1, g_h1);
    cudaGetSymbolAddress((void**)&agg1, g_agg1);
    cudaGetSymbolAddress((void**)&deg, g_deg);
    cudaGetSymbolAddress((void**)&rowptr, g_rowptr);
    cudaGetSymbolAddress((void**)&bsums, g_bsums);

    // --- edge dtype detection + degree + dinv -------------------------------
    k_detect<<<1, 32>>>(ei);
    k_init<<<(N + 255) / 256, 256>>>(N);
    k_count_deg<<<(E + 255) / 256, 256>>>(ei, E);
    k_dinv<<<(N + 255) / 256, 256>>>(N);

    // --- rowptr = exclusive_scan(deg) --------------------------------------
    int nb = (N + 255) / 256;                         // 196
    k_scan_blocks<<<nb, 256>>>(deg, rowptr, bsums, N);
    k_scan_sums<<<1, 256>>>(bsums, nb, rowptr + N);   // rowptr[N] = E+N
    k_scan_add<<<nb, 256>>>(rowptr, bsums, N);

    // --- CSR fill (edges + self loops) -------------------------------------
    k_fill_csr<<<(E + N + 255) / 256, 256>>>(ei, E, N);

    // --- layer 1: h1 = x @ W1 ; agg1 = relu(Anorm@h1 + b1) ------------------
    {
        dim3 grid((F_HID + 63) / 64, (N + 127) / 128);
        k_sgemm<false><<<grid, 256>>>(x, W1, nullptr, h1, N, F_HID, IN_CH);
    }
    k_aggregate<true><<<N, 128>>>(h1, b1, agg1, F_HID);

    // --- layer 2: agg2 = Anorm@agg1 (reuse h1) ; out = agg2@W2 + b2 ---------
    k_aggregate<false><<<N, 128>>>(agg1, nullptr, h1, F_HID);
    {
        dim3 grid((H2 + 63) / 64, (N + 127) / 128);
        k_sgemm<true><<<grid, 256>>>(h1, W2, b2, out, N, H2, F_HID);
    }
}

// round 3
// speedup vs baseline: 1.7260x; 1.7260x over previous
#include <cuda_runtime.h>
#include <cuda_bf16.h>
#include <stdint.h>

// ---------------------------------------------------------------------------
// GCN 2-layer:  out = Anorm @ relu(Anorm @ (x@W1) + b1) @ W2 + b2
// Layer 2 uses linearity: (Anorm @ h1relu) @ W2 + b2.
// GEMMs: tensor-core bf16 hi/lo split (3-mma Markidis) => ~fp32 accuracy.
// ---------------------------------------------------------------------------

#define N_NODES 50000
#define M_PAD   50048          // padded to multiple of 128
#define MAX_E   1600000
#define MAX_CSR (MAX_E + N_NODES)
#define F_HID   400
#define K1      512            // layer-1 GEMM K
#define N1P     512            // W1 N padded to 128-mult
#define K2P     416            // layer-2 GEMM K padded to 32-mult
#define N2P     896            // W2 N padded to 128-mult

// GEMM tiling
#define BM 128
#define BN 128
#define BK 32
#define AP 40                  // smem A row pitch (elems): 80B -> conflict-free ldmatrix
#define BP 136                 // smem B row pitch (elems): 272B -> conflict-free ldmatrix
#define GEMM_SMEM ((2*BM*AP + 2*BK*BP) * 2 * 2)   // 75776 bytes

// ------------------------------- scratch -----------------------------------
__device__ float g_h1[(size_t)N_NODES * F_HID];    // x@W1
__device__ float g_agg1[(size_t)N_NODES * F_HID];  // relu(agg(h1)+b1)
__device__ __nv_bfloat16 g_xhi[(size_t)M_PAD * K1];
__device__ __nv_bfloat16 g_xlo[(size_t)M_PAD * K1];
__device__ __nv_bfloat16 g_a2hi[(size_t)M_PAD * K2P];
__device__ __nv_bfloat16 g_a2lo[(size_t)M_PAD * K2P];
__device__ __nv_bfloat16 g_w1hi[K1 * N1P];
__device__ __nv_bfloat16 g_w1lo[K1 * N1P];
__device__ __nv_bfloat16 g_w2hi[K2P * N2P];
__device__ __nv_bfloat16 g_w2lo[K2P * N2P];
__device__ float g_dinv[N_NODES];
__device__ int   g_deg[N_NODES];
__device__ int   g_fill[N_NODES];
__device__ int   g_rowptr[N_NODES + 1];
__device__ int   g_csr[MAX_CSR];
__device__ int   g_bsums[512];
__device__ int   g_is64;

// ---------------------------------------------------------------------------
// edge dtype detection (int32 vs int64 delivery)
// ---------------------------------------------------------------------------
__global__ void k_detect(const void* __restrict__ ei) {
    if (threadIdx.x == 0 && blockIdx.x == 0) {
        const long long* p = (const long long*)ei;
        int ok64 = 1;
#pragma unroll
        for (int i = 0; i < 16; i++) {
            long long v = p[i];
            if (v < 0 || v >= N_NODES) ok64 = 0;
        }
        g_is64 = ok64;
    }
}

__device__ __forceinline__ int edge_at(const void* ei, size_t idx) {
    if (g_is64) return (int)((const long long*)ei)[idx];
    return ((const int*)ei)[idx];
}

// ---------------------------------------------------------------------------
// degree / dinv
// ---------------------------------------------------------------------------
__global__ void k_init(int n) {
    int i = blockIdx.x * blockDim.x + threadIdx.x;
    if (i < n) { g_deg[i] = 1; g_fill[i] = 0; }
}

__global__ void k_count_deg(const void* __restrict__ ei, int E) {
    int i = blockIdx.x * blockDim.x + threadIdx.x;
    if (i < E) {
        int d = edge_at(ei, (size_t)E + i);
        if ((unsigned)d < (unsigned)N_NODES) atomicAdd(&g_deg[d], 1);
    }
}

__global__ void k_dinv(int n) {
    int i = blockIdx.x * blockDim.x + threadIdx.x;
    if (i < n) g_dinv[i] = rsqrtf((float)g_deg[i]);
}

// ---------------------------------------------------------------------------
// exclusive scan of g_deg -> g_rowptr
// ---------------------------------------------------------------------------
__device__ __forceinline__ int warp_incl_scan(int v) {
#pragma unroll
    for (int o = 1; o < 32; o <<= 1) {
        int t = __shfl_up_sync(0xffffffffu, v, o);
        if ((threadIdx.x & 31) >= o) v += t;
    }
    return v;
}

__global__ void k_scan_blocks(const int* __restrict__ in, int* __restrict__ out,
                              int* __restrict__ bsums, int n) {
    __shared__ int wsum[8];
    int i = blockIdx.x * 256 + threadIdx.x;
    int v = (i < n) ? in[i] : 0;
    int inc = warp_incl_scan(v);
    int lane = threadIdx.x & 31, w = threadIdx.x >> 5;
    if (lane == 31) wsum[w] = inc;
    __syncthreads();
    if (w == 0) {
        int s = (lane < 8) ? wsum[lane] : 0;
        s = warp_incl_scan(s);
        if (lane < 8) wsum[lane] = s;
    }
    __syncthreads();
    int off = (w > 0) ? wsum[w - 1] : 0;
    if (i < n) out[i] = off + inc - v;
    if (threadIdx.x == 255) bsums[blockIdx.x] = off + inc;
}

__global__ void k_scan_sums(int* __restrict__ bsums, int nb, int* __restrict__ total_out) {
    __shared__ int wsum[8];
    int v = (threadIdx.x < nb) ? bsums[threadIdx.x] : 0;
    int inc = warp_incl_scan(v);
    int lane = threadIdx.x & 31, w = threadIdx.x >> 5;
    if (lane == 31) wsum[w] = inc;
    __syncthreads();
    if (w == 0) {
        int s = (lane < 8) ? wsum[lane] : 0;
        s = warp_incl_scan(s);
        if (lane < 8) wsum[lane] = s;
    }
    __syncthreads();
    int off = (w > 0) ? wsum[w - 1] : 0;
    if (threadIdx.x < nb) bsums[threadIdx.x] = off + inc - v;
    if (threadIdx.x == 255) *total_out = off + inc;
}

__global__ void k_scan_add(int* __restrict__ out, const int* __restrict__ bsums, int n) {
    int i = blockIdx.x * 256 + threadIdx.x;
    if (i < n) out[i] += bsums[blockIdx.x];
}

// ---------------------------------------------------------------------------
// CSR fill
// ---------------------------------------------------------------------------
__global__ void k_fill_csr(const void* __restrict__ ei, int E, int n) {
    int i = blockIdx.x * blockDim.x + threadIdx.x;
    int total = E + n;
    if (i >= total) return;
    int s, d;
    if (i < E) {
        s = edge_at(ei, i);
        d = edge_at(ei, (size_t)E + i);
        if ((unsigned)s >= (unsigned)n || (unsigned)d >= (unsigned)n) return;
    } else {
        s = d = i - E;
    }
    int pos = atomicAdd(&g_fill[d], 1);
    g_csr[g_rowptr[d] + pos] = s;
}

// ---------------------------------------------------------------------------
// hi/lo bf16 split conversions
// ---------------------------------------------------------------------------
__device__ __forceinline__ void split_bf16(float v, __nv_bfloat16& h, __nv_bfloat16& l) {
    h = __float2bfloat16(v);
    l = __float2bfloat16(v - __bfloat162float(h));
}

__global__ void k_conv_x(const float* __restrict__ x, int total) {
    int i = blockIdx.x * blockDim.x + threadIdx.x;
    if (i < total) {
        __nv_bfloat16 h, l;
        split_bf16(x[i], h, l);
        g_xhi[i] = h; g_xlo[i] = l;
    }
}

__global__ void k_conv_w1(const float* __restrict__ W1) {
    int i = blockIdx.x * blockDim.x + threadIdx.x;
    if (i < K1 * N1P) {
        int k = i / N1P, n = i % N1P;
        float v = (n < F_HID) ? W1[k * F_HID + n] : 0.f;
        __nv_bfloat16 h, l;
        split_bf16(v, h, l);
        g_w1hi[i] = h; g_w1lo[i] = l;
    }
}

__global__ void k_conv_w2(const float* __restrict__ W2, int N2real) {
    int i = blockIdx.x * blockDim.x + threadIdx.x;
    if (i < K2P * N2P) {
        int k = i / N2P, n = i % N2P;
        float v = (k < F_HID && n < N2real) ? W2[k * N2real + n] : 0.f;
        __nv_bfloat16 h, l;
        split_bf16(v, h, l);
        g_w2hi[i] = h; g_w2lo[i] = l;
    }
}

// ---------------------------------------------------------------------------
// tensor-core GEMM: C[M,Nreal] = A[M,K](hi+lo) * B[K,Nphys](hi+lo) (+bias)
// A rows padded to M_PAD (zero), K multiple of 32, Nphys multiple of 128.
// ---------------------------------------------------------------------------
__device__ __forceinline__ void cp16(void* dst, const void* src) {
    unsigned d = (unsigned)__cvta_generic_to_shared(dst);
    asm volatile("cp.async.cg.shared.global [%0], [%1], 16;\n" :: "r"(d), "l"(src));
}

__device__ __forceinline__ void ldmA(uint32_t* a, const __nv_bfloat16* p) {
    unsigned addr = (unsigned)__cvta_generic_to_shared(p);
    asm volatile("ldmatrix.sync.aligned.m8n8.x4.shared.b16 {%0,%1,%2,%3}, [%4];"
                 : "=r"(a[0]), "=r"(a[1]), "=r"(a[2]), "=r"(a[3]) : "r"(addr));
}

__device__ __forceinline__ void ldmB(uint32_t* b, const __nv_bfloat16* p) {
    unsigned addr = (unsigned)__cvta_generic_to_shared(p);
    asm volatile("ldmatrix.sync.aligned.m8n8.x2.trans.shared.b16 {%0,%1}, [%2];"
                 : "=r"(b[0]), "=r"(b[1]) : "r"(addr));
}

__device__ __forceinline__ void mma_bf16(float* c, const uint32_t* a, const uint32_t* b) {
    asm volatile("mma.sync.aligned.m16n8k16.row.col.f32.bf16.bf16.f32 "
                 "{%0,%1,%2,%3}, {%4,%5,%6,%7}, {%8,%9}, {%0,%1,%2,%3};"
                 : "+f"(c[0]), "+f"(c[1]), "+f"(c[2]), "+f"(c[3])
                 : "r"(a[0]), "r"(a[1]), "r"(a[2]), "r"(a[3]), "r"(b[0]), "r"(b[1]));
}

template <bool BIAS>
__global__ __launch_bounds__(256, 1) void k_mma_gemm(
    const __nv_bfloat16* __restrict__ Ahi, const __nv_bfloat16* __restrict__ Alo,
    const __nv_bfloat16* __restrict__ Bhi, const __nv_bfloat16* __restrict__ Blo,
    const float* __restrict__ bias, float* __restrict__ C,
    int M, int Nreal, int Nphys, int K) {
    extern __shared__ __nv_bfloat16 smem[];
    __nv_bfloat16* sAh = smem;                       // 2 stages * BM*AP
    __nv_bfloat16* sAl = sAh + 2 * BM * AP;
    __nv_bfloat16* sBh = sAl + 2 * BM * AP;          // 2 stages * BK*BP
    __nv_bfloat16* sBl = sBh + 2 * BK * BP;

    int tid = threadIdx.x;
    int lane = tid & 31, wid = tid >> 5;
    int wm = (wid >> 2) * 64;      // warp row offset within block tile
    int wn = (wid & 3) * 32;       // warp col offset
    int bm = blockIdx.y * BM, bn = blockIdx.x * BN;

    float acc[4][4][4];
#pragma unroll
    for (int i = 0; i < 4; i++)
#pragma unroll
        for (int j = 0; j < 4; j++)
#pragma unroll
            for (int k = 0; k < 4; k++) acc[i][j][k] = 0.f;

    const int nk = K / BK;

    auto load_stage = [&](int st, int kt) {
        __nv_bfloat16* ah = sAh + st * BM * AP;
        __nv_bfloat16* al = sAl + st * BM * AP;
        __nv_bfloat16* bh = sBh + st * BK * BP;
        __nv_bfloat16* bl = sBl + st * BK * BP;
#pragma unroll
        for (int i = 0; i < 2; i++) {
            int q = tid + i * 256;           // 512 chunks: 128 rows x 4x16B
            int r = q >> 2, c = q & 3;
            size_t goff = (size_t)(bm + r) * K + kt * BK + c * 8;
            cp16(ah + r * AP + c * 8, Ahi + goff);
            cp16(al + r * AP + c * 8, Alo + goff);
        }
#pragma unroll
        for (int i = 0; i < 2; i++) {
            int q = tid + i * 256;           // 512 chunks: 32 rows x 16x16B
            int r = q >> 4, c = q & 15;
            size_t goff = (size_t)(kt * BK + r) * Nphys + bn + c * 8;
            cp16(bh + r * BP + c * 8, Bhi + goff);
            cp16(bl + r * BP + c * 8, Blo + goff);
        }
        asm volatile("cp.async.commit_group;\n");
    };

    load_stage(0, 0);

    for (int kt = 0; kt < nk; kt++) {
        if (kt + 1 < nk) {
            load_stage((kt + 1) & 1, kt + 1);
            asm volatile("cp.async.wait_group 1;\n");
        } else {
            asm volatile("cp.async.wait_group 0;\n");
        }
        __syncthreads();

        int st = kt & 1;
        const __nv_bfloat16* ah = sAh + st * BM * AP;
        const __nv_bfloat16* al = sAl + st * BM * AP;
        const __nv_bfloat16* bh = sBh + st * BK * BP;
        const __nv_bfloat16* bl = sBl + st * BK * BP;

#pragma unroll
        for (int ks = 0; ks < 2; ks++) {
            uint32_t Ah[4][4], Al[4][4], Bh[4][2], Bl[4][2];
            int arow = (lane & 15), ahalf = (lane >> 4);
#pragma unroll
            for (int mt = 0; mt < 4; mt++) {
                const __nv_bfloat16* pa =
                    ah + (size_t)(wm + mt * 16 + arow) * AP + ks * 16 + ahalf * 8;
                const __nv_bfloat16* pl =
                    al + (size_t)(wm + mt * 16 + arow) * AP + ks * 16 + ahalf * 8;
                ldmA(Ah[mt], pa);
                ldmA(Al[mt], pl);
            }
#pragma unroll
            for (int nt = 0; nt < 4; nt++) {
                const __nv_bfloat16* pb =
                    bh + (size_t)(ks * 16 + (lane & 15)) * BP + wn + nt * 8;
                const __nv_bfloat16* ql =
                    bl + (size_t)(ks * 16 + (lane & 15)) * BP + wn + nt * 8;
                ldmB(Bh[nt], pb);
                ldmB(Bl[nt], ql);
            }
#pragma unroll
            for (int mt = 0; mt < 4; mt++)
#pragma unroll
                for (int nt = 0; nt < 4; nt++) {
                    mma_bf16(acc[mt][nt], Ah[mt], Bh[nt]);
                    mma_bf16(acc[mt][nt], Ah[mt], Bl[nt]);
                    mma_bf16(acc[mt][nt], Al[mt], Bh[nt]);
                }
        }
        __syncthreads();
    }

    // epilogue
#pragma unroll
    for (int mt = 0; mt < 4; mt++) {
#pragma unroll
        for (int nt = 0; nt < 4; nt++) {
#pragma unroll
            for (int i = 0; i < 4; i++) {
                int row = bm + wm + mt * 16 + (lane >> 2) + (i >> 1) * 8;
                int col = bn + wn + nt * 8 + (lane & 3) * 2 + (i & 1);
                if (row < M && col < Nreal) {
                    float v = acc[mt][nt][i];
                    if (BIAS) v += bias[col];
                    C[(size_t)row * Nreal + col] = v;
                }
            }
        }
    }
}

// ---------------------------------------------------------------------------
// CSR aggregation over F=400 features, one block (128 thr) per node.
// ---------------------------------------------------------------------------
template <bool RELU, bool BF16OUT>
__global__ __launch_bounds__(128) void k_aggregate(
    const float* __restrict__ H, const float* __restrict__ bias,
    float* __restrict__ out, __nv_bfloat16* __restrict__ outHi,
    __nv_bfloat16* __restrict__ outLo) {
    __shared__ int   s_idx[128];
    __shared__ float s_w[128];

    const int F = F_HID;
    int node = blockIdx.x;
    int tid = threadIdx.x;
    int start = g_rowptr[node], end = g_rowptr[node + 1];
    float dd = g_dinv[node];

    float acc[4] = {0.f, 0.f, 0.f, 0.f};

    for (int base = start; base < end; base += 128) {
        int cnt = min(128, end - base);
        if (tid < cnt) {
            int s = g_csr[base + tid];
            s_idx[tid] = s;
            s_w[tid] = g_dinv[s] * dd;
        }
        __syncthreads();
        for (int j = 0; j < cnt; j++) {
            const float* hr = H + (size_t)s_idx[j] * F;
            float w = s_w[j];
#pragma unroll
            for (int k = 0; k < 4; k++) {
                int f = tid + k * 128;
                if (f < F) acc[k] += hr[f] * w;
            }
        }
        __syncthreads();
    }

#pragma unroll
    for (int k = 0; k < 4; k++) {
        int f = tid + k * 128;
        if (f < F) {
            float v = acc[k];
            if (bias) v += bias[f];
            if (RELU) v = fmaxf(v, 0.f);
            if (BF16OUT) {
                __nv_bfloat16 h, l;
                split_bf16(v, h, l);
                outHi[(size_t)node * K2P + f] = h;
                outLo[(size_t)node * K2P + f] = l;
            } else {
                out[(size_t)node * F + f] = v;
            }
        }
    }
}

// ---------------------------------------------------------------------------
// launch
// ---------------------------------------------------------------------------
extern "C" void kernel_launch(void* const* d_in, const int* in_sizes, int n_in,
                              void* d_out, int out_size) {
    const float* x  = (const float*)d_in[0];
    const void*  ei = d_in[1];
    const float* W1 = (const float*)d_in[2];
    const float* b1 = (const float*)d_in[3];
    const float* W2 = (const float*)d_in[4];
    const float* b2 = (const float*)d_in[5];
    float* out = (float*)d_out;

    const int N = N_NODES;
    const int E = in_sizes[1] / 2;
    const int H2 = in_sizes[5];                       // 800

    float *h1, *agg1;
    __nv_bfloat16 *xhi, *xlo, *a2hi, *a2lo, *w1hi, *w1lo, *w2hi, *w2lo;
    int *deg, *rowptr, *bsums;
    cudaGetSymbolAddress((void**)&h1, g_h1);
    cudaGetSymbolAddress((void**)&agg1, g_agg1);
    cudaGetSymbolAddress((void**)&xhi, g_xhi);
    cudaGetSymbolAddress((void**)&xlo, g_xlo);
    cudaGetSymbolAddress((void**)&a2hi, g_a2hi);
    cudaGetSymbolAddress((void**)&a2lo, g_a2lo);
    cudaGetSymbolAddress((void**)&w1hi, g_w1hi);
    cudaGetSymbolAddress((void**)&w1lo, g_w1lo);
    cudaGetSymbolAddress((void**)&w2hi, g_w2hi);
    cudaGetSymbolAddress((void**)&w2lo, g_w2lo);
    cudaGetSymbolAddress((void**)&deg, g_deg);
    cudaGetSymbolAddress((void**)&rowptr, g_rowptr);
    cudaGetSymbolAddress((void**)&bsums, g_bsums);

    static int smem_set = 0;
    if (!smem_set) {
        cudaFuncSetAttribute(k_mma_gemm<false>,
                             cudaFuncAttributeMaxDynamicSharedMemorySize, GEMM_SMEM);
        cudaFuncSetAttribute(k_mma_gemm<true>,
                             cudaFuncAttributeMaxDynamicSharedMemorySize, GEMM_SMEM);
        smem_set = 1;
    }

    // --- edge dtype detection + degree + dinv -------------------------------
    k_detect<<<1, 32>>>(ei);
    k_init<<<(N + 255) / 256, 256>>>(N);
    k_count_deg<<<(E + 255) / 256, 256>>>(ei, E);
    k_dinv<<<(N + 255) / 256, 256>>>(N);

    // --- rowptr = exclusive_scan(deg) ---------------------------------------
    int nb = (N + 255) / 256;
    k_scan_blocks<<<nb, 256>>>(deg, rowptr, bsums, N);
    k_scan_sums<<<1, 256>>>(bsums, nb, rowptr + N);
    k_scan_add<<<nb, 256>>>(rowptr, bsums, N);

    // --- CSR fill ------------------------------------------------------------
    k_fill_csr<<<(E + N + 255) / 256, 256>>>(ei, E, N);

    // --- conversions (independent of CSR) ------------------------------------
    k_conv_x<<<(N * K1 + 255) / 256, 256>>>(x, N * K1);
    k_conv_w1<<<(K1 * N1P + 255) / 256, 256>>>(W1);
    k_conv_w2<<<(K2P * N2P + 255) / 256, 256>>>(W2, H2);

    // --- layer 1: h1 = x @ W1 (tensor core) ; agg1 = relu(Anorm@h1 + b1) -----
    {
        dim3 grid(N1P / BN, (N + BM - 1) / BM);   // 4 x 391
        k_mma_gemm<false><<<grid, 256, GEMM_SMEM>>>(
            xhi, xlo, w1hi, w1lo, nullptr, h1, N, F_HID, N1P, K1);
    }
    k_aggregate<true, false><<<N, 128>>>(h1, b1, agg1, nullptr, nullptr);

    // --- layer 2: agg2(bf16 hi/lo) = Anorm@agg1 ; out = agg2@W2 + b2 ---------
    k_aggregate<false, true><<<N, 128>>>(agg1, nullptr, nullptr, a2hi, a2lo);
    {
        dim3 grid(N2P / BN, (N + BM - 1) / BM);   // 7 x 391
        k_mma_gemm<true><<<grid, 256, GEMM_SMEM>>>(
            a2hi, a2lo, w2hi, w2lo, b2, out, N, H2, N2P, K2P);
    }
}

// round 4
// speedup vs baseline: 1.9233x; 1.1143x over previous
#include <cuda_runtime.h>
#include <cuda_bf16.h>
#include <stdint.h>

// ---------------------------------------------------------------------------
// GCN 2-layer:  out = Anorm @ relu(Anorm @ (x@W1) + b1) @ W2 + b2
// Layer 2 uses linearity: (Anorm @ h1relu) @ W2 + b2.
// GEMMs: tensor-core bf16 hi/lo split (3-mma Markidis) => ~fp32 accuracy.
// R4: dual-stream overlap (CSR build || conv+GEMM1), float4 aggregation.
// ---------------------------------------------------------------------------

#define N_NODES 50000
#define M_PAD   50048          // padded to multiple of 128
#define MAX_E   1600000
#define MAX_CSR (MAX_E + N_NODES)
#define F_HID   400
#define K1      512            // layer-1 GEMM K
#define N1P     512            // W1 N padded to 128-mult
#define K2P     416            // layer-2 GEMM K padded to 32-mult
#define N2P     896            // W2 N padded to 128-mult

// GEMM tiling
#define BM 128
#define BN 128
#define BK 32
#define AP 40                  // smem A row pitch (elems): 80B -> conflict-free ldmatrix
#define BP 136                 // smem B row pitch (elems): 272B -> conflict-free ldmatrix
#define GEMM_SMEM ((2*BM*AP + 2*BK*BP) * 2 * 2)   // 75776 bytes

// ------------------------------- scratch -----------------------------------
__device__ float g_h1[(size_t)N_NODES * F_HID];    // x@W1
__device__ float g_agg1[(size_t)N_NODES * F_HID];  // relu(agg(h1)+b1)
__device__ __nv_bfloat16 g_xhi[(size_t)M_PAD * K1];
__device__ __nv_bfloat16 g_xlo[(size_t)M_PAD * K1];
__device__ __nv_bfloat16 g_a2hi[(size_t)M_PAD * K2P];
__device__ __nv_bfloat16 g_a2lo[(size_t)M_PAD * K2P];
__device__ __nv_bfloat16 g_w1hi[K1 * N1P];
__device__ __nv_bfloat16 g_w1lo[K1 * N1P];
__device__ __nv_bfloat16 g_w2hi[K2P * N2P];
__device__ __nv_bfloat16 g_w2lo[K2P * N2P];
__device__ float g_dinv[N_NODES];
__device__ int   g_deg[N_NODES];
__device__ int   g_fill[N_NODES];
__device__ int   g_rowptr[N_NODES + 1];
__device__ int   g_csr[MAX_CSR];
__device__ int   g_bsums[512];
__device__ int   g_is64;

// ---------------------------------------------------------------------------
// edge dtype detection (int32 vs int64 delivery)
// ---------------------------------------------------------------------------
__global__ void k_detect(const void* __restrict__ ei) {
    if (threadIdx.x == 0 && blockIdx.x == 0) {
        const long long* p = (const long long*)ei;
        int ok64 = 1;
#pragma unroll
        for (int i = 0; i < 16; i++) {
            long long v = p[i];
            if (v < 0 || v >= N_NODES) ok64 = 0;
        }
        g_is64 = ok64;
    }
}

__device__ __forceinline__ int edge_at(const void* ei, size_t idx) {
    if (g_is64) return (int)((const long long*)ei)[idx];
    return ((const int*)ei)[idx];
}

// ---------------------------------------------------------------------------
// degree / dinv
// ---------------------------------------------------------------------------
__global__ void k_init(int n) {
    int i = blockIdx.x * blockDim.x + threadIdx.x;
    if (i < n) { g_deg[i] = 1; g_fill[i] = 0; }
}

__global__ void k_count_deg(const void* __restrict__ ei, int E) {
    int i = blockIdx.x * blockDim.x + threadIdx.x;
    if (i < E) {
        int d = edge_at(ei, (size_t)E + i);
        if ((unsigned)d < (unsigned)N_NODES) atomicAdd(&g_deg[d], 1);
    }
}

__global__ void k_dinv(int n) {
    int i = blockIdx.x * blockDim.x + threadIdx.x;
    if (i < n) g_dinv[i] = rsqrtf((float)g_deg[i]);
}

// ---------------------------------------------------------------------------
// exclusive scan of g_deg -> g_rowptr
// ---------------------------------------------------------------------------
__device__ __forceinline__ int warp_incl_scan(int v) {
#pragma unroll
    for (int o = 1; o < 32; o <<= 1) {
        int t = __shfl_up_sync(0xffffffffu, v, o);
        if ((threadIdx.x & 31) >= o) v += t;
    }
    return v;
}

__global__ void k_scan_blocks(const int* __restrict__ in, int* __restrict__ out,
                              int* __restrict__ bsums, int n) {
    __shared__ int wsum[8];
    int i = blockIdx.x * 256 + threadIdx.x;
    int v = (i < n) ? in[i] : 0;
    int inc = warp_incl_scan(v);
    int lane = threadIdx.x & 31, w = threadIdx.x >> 5;
    if (lane == 31) wsum[w] = inc;
    __syncthreads();
    if (w == 0) {
        int s = (lane < 8) ? wsum[lane] : 0;
        s = warp_incl_scan(s);
        if (lane < 8) wsum[lane] = s;
    }
    __syncthreads();
    int off = (w > 0) ? wsum[w - 1] : 0;
    if (i < n) out[i] = off + inc - v;
    if (threadIdx.x == 255) bsums[blockIdx.x] = off + inc;
}

__global__ void k_scan_sums(int* __restrict__ bsums, int nb, int* __restrict__ total_out) {
    __shared__ int wsum[8];
    int v = (threadIdx.x < nb) ? bsums[threadIdx.x] : 0;
    int inc = warp_incl_scan(v);
    int lane = threadIdx.x & 31, w = threadIdx.x >> 5;
    if (lane == 31) wsum[w] = inc;
    __syncthreads();
    if (w == 0) {
        int s = (lane < 8) ? wsum[lane] : 0;
        s = warp_incl_scan(s);
        if (lane < 8) wsum[lane] = s;
    }
    __syncthreads();
    int off = (w > 0) ? wsum[w - 1] : 0;
    if (threadIdx.x < nb) bsums[threadIdx.x] = off + inc - v;
    if (threadIdx.x == 255) *total_out = off + inc;
}

__global__ void k_scan_add(int* __restrict__ out, const int* __restrict__ bsums, int n) {
    int i = blockIdx.x * 256 + threadIdx.x;
    if (i < n) out[i] += bsums[blockIdx.x];
}

// ---------------------------------------------------------------------------
// CSR fill
// ---------------------------------------------------------------------------
__global__ void k_fill_csr(const void* __restrict__ ei, int E, int n) {
    int i = blockIdx.x * blockDim.x + threadIdx.x;
    int total = E + n;
    if (i >= total) return;
    int s, d;
    if (i < E) {
        s = edge_at(ei, i);
        d = edge_at(ei, (size_t)E + i);
        if ((unsigned)s >= (unsigned)n || (unsigned)d >= (unsigned)n) return;
    } else {
        s = d = i - E;
    }
    int pos = atomicAdd(&g_fill[d], 1);
    g_csr[g_rowptr[d] + pos] = s;
}

// ---------------------------------------------------------------------------
// hi/lo bf16 split conversions
// ---------------------------------------------------------------------------
__device__ __forceinline__ void split_bf16(float v, __nv_bfloat16& h, __nv_bfloat16& l) {
    h = __float2bfloat16(v);
    l = __float2bfloat16(v - __bfloat162float(h));
}

__global__ void k_conv_x(const float* __restrict__ x, int total) {
    int i = blockIdx.x * blockDim.x + threadIdx.x;
    if (i < total) {
        __nv_bfloat16 h, l;
        split_bf16(x[i], h, l);
        g_xhi[i] = h; g_xlo[i] = l;
    }
}

__global__ void k_conv_w1(const float* __restrict__ W1) {
    int i = blockIdx.x * blockDim.x + threadIdx.x;
    if (i < K1 * N1P) {
        int k = i / N1P, n = i % N1P;
        float v = (n < F_HID) ? W1[k * F_HID + n] : 0.f;
        __nv_bfloat16 h, l;
        split_bf16(v, h, l);
        g_w1hi[i] = h; g_w1lo[i] = l;
    }
}

__global__ void k_conv_w2(const float* __restrict__ W2, int N2real) {
    int i = blockIdx.x * blockDim.x + threadIdx.x;
    if (i < K2P * N2P) {
        int k = i / N2P, n = i % N2P;
        float v = (k < F_HID && n < N2real) ? W2[k * N2real + n] : 0.f;
        __nv_bfloat16 h, l;
        split_bf16(v, h, l);
        g_w2hi[i] = h; g_w2lo[i] = l;
    }
}

// ---------------------------------------------------------------------------
// tensor-core GEMM: C[M,Nreal] = A[M,K](hi+lo) * B[K,Nphys](hi+lo) (+bias)
// ---------------------------------------------------------------------------
__device__ __forceinline__ void cp16(void* dst, const void* src) {
    unsigned d = (unsigned)__cvta_generic_to_shared(dst);
    asm volatile("cp.async.cg.shared.global [%0], [%1], 16;\n" :: "r"(d), "l"(src));
}

__device__ __forceinline__ void ldmA(uint32_t* a, const __nv_bfloat16* p) {
    unsigned addr = (unsigned)__cvta_generic_to_shared(p);
    asm volatile("ldmatrix.sync.aligned.m8n8.x4.shared.b16 {%0,%1,%2,%3}, [%4];"
                 : "=r"(a[0]), "=r"(a[1]), "=r"(a[2]), "=r"(a[3]) : "r"(addr));
}

__device__ __forceinline__ void ldmB(uint32_t* b, const __nv_bfloat16* p) {
    unsigned addr = (unsigned)__cvta_generic_to_shared(p);
    asm volatile("ldmatrix.sync.aligned.m8n8.x2.trans.shared.b16 {%0,%1}, [%2];"
                 : "=r"(b[0]), "=r"(b[1]) : "r"(addr));
}

__device__ __forceinline__ void mma_bf16(float* c, const uint32_t* a, const uint32_t* b) {
    asm volatile("mma.sync.aligned.m16n8k16.row.col.f32.bf16.bf16.f32 "
                 "{%0,%1,%2,%3}, {%4,%5,%6,%7}, {%8,%9}, {%0,%1,%2,%3};"
                 : "+f"(c[0]), "+f"(c[1]), "+f"(c[2]), "+f"(c[3])
                 : "r"(a[0]), "r"(a[1]), "r"(a[2]), "r"(a[3]), "r"(b[0]), "r"(b[1]));
}

template <bool BIAS>
__global__ __launch_bounds__(256, 1) void k_mma_gemm(
    const __nv_bfloat16* __restrict__ Ahi, const __nv_bfloat16* __restrict__ Alo,
    const __nv_bfloat16* __restrict__ Bhi, const __nv_bfloat16* __restrict__ Blo,
    const float* __restrict__ bias, float* __restrict__ C,
    int M, int Nreal, int Nphys, int K) {
    extern __shared__ __nv_bfloat16 smem[];
    __nv_bfloat16* sAh = smem;
    __nv_bfloat16* sAl = sAh + 2 * BM * AP;
    __nv_bfloat16* sBh = sAl + 2 * BM * AP;
    __nv_bfloat16* sBl = sBh + 2 * BK * BP;

    int tid = threadIdx.x;
    int lane = tid & 31, wid = tid >> 5;
    int wm = (wid >> 2) * 64;
    int wn = (wid & 3) * 32;
    int bm = blockIdx.y * BM, bn = blockIdx.x * BN;

    float acc[4][4][4];
#pragma unroll
    for (int i = 0; i < 4; i++)
#pragma unroll
        for (int j = 0; j < 4; j++)
#pragma unroll
            for (int k = 0; k < 4; k++) acc[i][j][k] = 0.f;

    const int nk = K / BK;

    auto load_stage = [&](int st, int kt) {
        __nv_bfloat16* ah = sAh + st * BM * AP;
        __nv_bfloat16* al = sAl + st * BM * AP;
        __nv_bfloat16* bh = sBh + st * BK * BP;
        __nv_bfloat16* bl = sBl + st * BK * BP;
#pragma unroll
        for (int i = 0; i < 2; i++) {
            int q = tid + i * 256;
            int r = q >> 2, c = q & 3;
            size_t goff = (size_t)(bm + r) * K + kt * BK + c * 8;
            cp16(ah + r * AP + c * 8, Ahi + goff);
            cp16(al + r * AP + c * 8, Alo + goff);
        }
#pragma unroll
        for (int i = 0; i < 2; i++) {
            int q = tid + i * 256;
            int r = q >> 4, c = q & 15;
            size_t goff = (size_t)(kt * BK + r) * Nphys + bn + c * 8;
            cp16(bh + r * BP + c * 8, Bhi + goff);
            cp16(bl + r * BP + c * 8, Blo + goff);
        }
        asm volatile("cp.async.commit_group;\n");
    };

    load_stage(0, 0);

    for (int kt = 0; kt < nk; kt++) {
        if (kt + 1 < nk) {
            load_stage((kt + 1) & 1, kt + 1);
            asm volatile("cp.async.wait_group 1;\n");
        } else {
            asm volatile("cp.async.wait_group 0;\n");
        }
        __syncthreads();

        int st = kt & 1;
        const __nv_bfloat16* ah = sAh + st * BM * AP;
        const __nv_bfloat16* al = sAl + st * BM * AP;
        const __nv_bfloat16* bh = sBh + st * BK * BP;
        const __nv_bfloat16* bl = sBl + st * BK * BP;

#pragma unroll
        for (int ks = 0; ks < 2; ks++) {
            uint32_t Ah[4][4], Al[4][4], Bh[4][2], Bl[4][2];
            int arow = (lane & 15), ahalf = (lane >> 4);
#pragma unroll
            for (int mt = 0; mt < 4; mt++) {
                const __nv_bfloat16* pa =
                    ah + (size_t)(wm + mt * 16 + arow) * AP + ks * 16 + ahalf * 8;
                const __nv_bfloat16* pl =
                    al + (size_t)(wm + mt * 16 + arow) * AP + ks * 16 + ahalf * 8;
                ldmA(Ah[mt], pa);
                ldmA(Al[mt], pl);
            }
#pragma unroll
            for (int nt = 0; nt < 4; nt++) {
                const __nv_bfloat16* pb =
                    bh + (size_t)(ks * 16 + (lane & 15)) * BP + wn + nt * 8;
                const __nv_bfloat16* ql =
                    bl + (size_t)(ks * 16 + (lane & 15)) * BP + wn + nt * 8;
                ldmB(Bh[nt], pb);
                ldmB(Bl[nt], ql);
            }
#pragma unroll
            for (int mt = 0; mt < 4; mt++)
#pragma unroll
                for (int nt = 0; nt < 4; nt++) {
                    mma_bf16(acc[mt][nt], Ah[mt], Bh[nt]);
                    mma_bf16(acc[mt][nt], Ah[mt], Bl[nt]);
                    mma_bf16(acc[mt][nt], Al[mt], Bh[nt]);
                }
        }
        __syncthreads();
    }

#pragma unroll
    for (int mt = 0; mt < 4; mt++) {
#pragma unroll
        for (int nt = 0; nt < 4; nt++) {
#pragma unroll
            for (int i = 0; i < 4; i++) {
                int row = bm + wm + mt * 16 + (lane >> 2) + (i >> 1) * 8;
                int col = bn + wn + nt * 8 + (lane & 3) * 2 + (i & 1);
                if (row < M && col < Nreal) {
                    float v = acc[mt][nt][i];
                    if (BIAS) v += bias[col];
                    C[(size_t)row * Nreal + col] = v;
                }
            }
        }
    }
}

// ---------------------------------------------------------------------------
// CSR aggregation over F=400 features, one block (128 thr) per node.
// float4 path: threads 0..99 each own 4 contiguous features (LDG.128).
// ---------------------------------------------------------------------------
template <bool RELU, bool BF16OUT>
__global__ __launch_bounds__(128) void k_aggregate(
    const float* __restrict__ H, const float* __restrict__ bias,
    float* __restrict__ out, __nv_bfloat16* __restrict__ outHi,
    __nv_bfloat16* __restrict__ outLo) {
    __shared__ int   s_idx[128];
    __shared__ float s_w[128];

    int node = blockIdx.x;
    int tid = threadIdx.x;
    int start = g_rowptr[node], end = g_rowptr[node + 1];
    float dd = g_dinv[node];

    float4 acc = make_float4(0.f, 0.f, 0.f, 0.f);
    const bool active = tid < (F_HID / 4);   // 100 float4 lanes

    for (int base = start; base < end; base += 128) {
        int cnt = min(128, end - base);
        if (tid < cnt) {
            int s = g_csr[base + tid];
            s_idx[tid] = s;
            s_w[tid] = g_dinv[s] * dd;
        }
        __syncthreads();
        if (active) {
            int j = 0;
            for (; j + 2 <= cnt; j += 2) {
                const float4* h0 = (const float4*)(H + (size_t)s_idx[j] * F_HID);
                const float4* h1p = (const float4*)(H + (size_t)s_idx[j + 1] * F_HID);
                float w0 = s_w[j], w1 = s_w[j + 1];
                float4 v0 = h0[tid], v1 = h1p[tid];
                acc.x += v0.x * w0; acc.y += v0.y * w0;
                acc.z += v0.z * w0; acc.w += v0.w * w0;
                acc.x += v1.x * w1; acc.y += v1.y * w1;
                acc.z += v1.z * w1; acc.w += v1.w * w1;
            }
            if (j < cnt) {
                const float4* h0 = (const float4*)(H + (size_t)s_idx[j] * F_HID);
                float w0 = s_w[j];
                float4 v0 = h0[tid];
                acc.x += v0.x * w0; acc.y += v0.y * w0;
                acc.z += v0.z * w0; acc.w += v0.w * w0;
            }
        }
        __syncthreads();
    }

    if (active) {
        if (bias) {
            float4 b = ((const float4*)bias)[tid];
            acc.x += b.x; acc.y += b.y; acc.z += b.z; acc.w += b.w;
        }
        if (RELU) {
            acc.x = fmaxf(acc.x, 0.f); acc.y = fmaxf(acc.y, 0.f);
            acc.z = fmaxf(acc.z, 0.f); acc.w = fmaxf(acc.w, 0.f);
        }
        if (BF16OUT) {
            float v[4] = {acc.x, acc.y, acc.z, acc.w};
            __nv_bfloat16 hh[4], ll[4];
#pragma unroll
            for (int k = 0; k < 4; k++) split_bf16(v[k], hh[k], ll[k]);
            *(uint2*)(outHi + (size_t)node * K2P + tid * 4) = *(uint2*)hh;
            *(uint2*)(outLo + (size_t)node * K2P + tid * 4) = *(uint2*)ll;
        } else {
            ((float4*)(out + (size_t)node * F_HID))[tid] = acc;
        }
    }
}

// ---------------------------------------------------------------------------
// launch
// ---------------------------------------------------------------------------
extern "C" void kernel_launch(void* const* d_in, const int* in_sizes, int n_in,
                              void* d_out, int out_size) {
    const float* x  = (const float*)d_in[0];
    const void*  ei = d_in[1];
    const float* W1 = (const float*)d_in[2];
    const float* b1 = (const float*)d_in[3];
    const float* W2 = (const float*)d_in[4];
    const float* b2 = (const float*)d_in[5];
    float* out = (float*)d_out;

    const int N = N_NODES;
    const int E = in_sizes[1] / 2;
    const int H2 = in_sizes[5];                       // 800

    float *h1, *agg1;
    __nv_bfloat16 *xhi, *xlo, *a2hi, *a2lo, *w1hi, *w1lo, *w2hi, *w2lo;
    int *deg, *rowptr, *bsums;
    cudaGetSymbolAddress((void**)&h1, g_h1);
    cudaGetSymbolAddress((void**)&agg1, g_agg1);
    cudaGetSymbolAddress((void**)&xhi, g_xhi);
    cudaGetSymbolAddress((void**)&xlo, g_xlo);
    cudaGetSymbolAddress((void**)&a2hi, g_a2hi);
    cudaGetSymbolAddress((void**)&a2lo, g_a2lo);
    cudaGetSymbolAddress((void**)&w1hi, g_w1hi);
    cudaGetSymbolAddress((void**)&w1lo, g_w1lo);
    cudaGetSymbolAddress((void**)&w2hi, g_w2hi);
    cudaGetSymbolAddress((void**)&w2lo, g_w2lo);
    cudaGetSymbolAddress((void**)&deg, g_deg);
    cudaGetSymbolAddress((void**)&rowptr, g_rowptr);
    cudaGetSymbolAddress((void**)&bsums, g_bsums);

    static int inited = 0;
    static cudaStream_t s2;
    static cudaEvent_t evRoot, evCsr;
    if (!inited) {
        cudaFuncSetAttribute(k_mma_gemm<false>,
                             cudaFuncAttributeMaxDynamicSharedMemorySize, GEMM_SMEM);
        cudaFuncSetAttribute(k_mma_gemm<true>,
                             cudaFuncAttributeMaxDynamicSharedMemorySize, GEMM_SMEM);
        cudaStreamCreateWithFlags(&s2, cudaStreamNonBlocking);
        cudaEventCreateWithFlags(&evRoot, cudaEventDisableTiming);
        cudaEventCreateWithFlags(&evCsr, cudaEventDisableTiming);
        inited = 1;
    }

    // ---- fork: CSR build chain on s2, conversions+GEMM1 on main ------------
    cudaEventRecord(evRoot, 0);
    cudaStreamWaitEvent(s2, evRoot, 0);

    // s2: edge dtype + degree + dinv + scan + CSR fill
    k_detect<<<1, 32, 0, s2>>>(ei);
    k_init<<<(N + 255) / 256, 256, 0, s2>>>(N);
    k_count_deg<<<(E + 255) / 256, 256, 0, s2>>>(ei, E);
    k_dinv<<<(N + 255) / 256, 256, 0, s2>>>(N);
    int nb = (N + 255) / 256;
    k_scan_blocks<<<nb, 256, 0, s2>>>(deg, rowptr, bsums, N);
    k_scan_sums<<<1, 256, 0, s2>>>(bsums, nb, rowptr + N);
    k_scan_add<<<nb, 256, 0, s2>>>(rowptr, bsums, N);
    k_fill_csr<<<(E + N + 255) / 256, 256, 0, s2>>>(ei, E, N);
    cudaEventRecord(evCsr, s2);

    // main: conversions + GEMM1
    k_conv_x<<<(N * K1 + 255) / 256, 256>>>(x, N * K1);
    k_conv_w1<<<(K1 * N1P + 255) / 256, 256>>>(W1);
    k_conv_w2<<<(K2P * N2P + 255) / 256, 256>>>(W2, H2);
    {
        dim3 grid(N1P / BN, (N + BM - 1) / BM);
        k_mma_gemm<false><<<grid, 256, GEMM_SMEM>>>(
            xhi, xlo, w1hi, w1lo, nullptr, h1, N, F_HID, N1P, K1);
    }

    // ---- join: aggregations need CSR ---------------------------------------
    cudaStreamWaitEvent(0, evCsr, 0);

    k_aggregate<true, false><<<N, 128>>>(h1, b1, agg1, nullptr, nullptr);
    k_aggregate<false, true><<<N, 128>>>(agg1, nullptr, nullptr, a2hi, a2lo);
    {
        dim3 grid(N2P / BN, (N + BM - 1) / BM);
        k_mma_gemm<true><<<grid, 256, GEMM_SMEM>>>(
            a2hi, a2lo, w2hi, w2lo, b2, out, N, H2, N2P, K2P);
    }
}

// round 7
// speedup vs baseline: 1.9492x; 1.0135x over previous
#include <cuda_runtime.h>
#include <cuda_bf16.h>
#include <stdint.h>

// ---------------------------------------------------------------------------
// GCN 2-layer:  out = Anorm @ relu(Anorm @ (x@W1) + b1) @ W2 + b2
// Layer 2 via linearity: (Anorm @ h1relu) @ W2 + b2.
// GEMMs: mma.sync bf16 hi/lo split (3-mma Markidis) — tcgen05 rejected by
// harness toolchain (compute_103 PTX target), HMMA path is the ceiling here.
// R6: chunked agg2||GEMM2 overlap, x4-unrolled gather, conv_w2t off crit path.
// ---------------------------------------------------------------------------

#define N_NODES 50000
#define M_PAD   50048          // padded to multiple of 128
#define MAX_E   1600000
#define MAX_CSR (MAX_E + N_NODES)
#define F_HID   400
#define K1      512            // layer-1 GEMM K
#define N1P     512            // W1 N padded to 128-mult
#define K2P     416            // layer-2 GEMM K padded to 32-mult
#define N2P     896            // W2 N padded to 128-mult
#define SPLIT_R 25088          // GEMM2/agg2 chunk boundary (196 * 128)

// GEMM tiling
#define BM 128
#define BN 128
#define BK 32
#define AP 40                  // smem A row pitch (elems): 80B -> conflict-free ldmatrix
#define BP 136                 // smem B row pitch (elems): 272B -> conflict-free ldmatrix
#define GEMM_SMEM ((2*BM*AP + 2*BK*BP) * 2 * 2)   // 75776 bytes

// ------------------------------- scratch -----------------------------------
__device__ float g_h1[(size_t)N_NODES * F_HID];    // x@W1
__device__ float g_agg1[(size_t)N_NODES * F_HID];  // relu(agg(h1)+b1)
__device__ __nv_bfloat16 g_xhi[(size_t)M_PAD * K1];
__device__ __nv_bfloat16 g_xlo[(size_t)M_PAD * K1];
__device__ __nv_bfloat16 g_a2hi[(size_t)M_PAD * K2P];   // pad cols 400..415 stay 0
__device__ __nv_bfloat16 g_a2lo[(size_t)M_PAD * K2P];
__device__ __nv_bfloat16 g_w1hi[K1 * N1P];
__device__ __nv_bfloat16 g_w1lo[K1 * N1P];
__device__ __nv_bfloat16 g_w2hi[K2P * N2P];
__device__ __nv_bfloat16 g_w2lo[K2P * N2P];
__device__ float g_dinv[N_NODES];
__device__ int   g_deg[N_NODES];
__device__ int   g_fill[N_NODES];
__device__ int   g_rowptr[N_NODES + 1];
__device__ int   g_csr[MAX_CSR];
__device__ int   g_bsums[512];
__device__ int   g_is64;

// ---------------------------------------------------------------------------
// edge dtype detection (int32 vs int64 delivery)
// ---------------------------------------------------------------------------
__global__ void k_detect(const void* __restrict__ ei) {
    if (threadIdx.x == 0 && blockIdx.x == 0) {
        const long long* p = (const long long*)ei;
        int ok64 = 1;
#pragma unroll
        for (int i = 0; i < 16; i++) {
            long long v = p[i];
            if (v < 0 || v >= N_NODES) ok64 = 0;
        }
        g_is64 = ok64;
    }
}

__device__ __forceinline__ int edge_at(const void* ei, size_t idx) {
    if (g_is64) return (int)((const long long*)ei)[idx];
    return ((const int*)ei)[idx];
}

// ---------------------------------------------------------------------------
// degree / dinv
// ---------------------------------------------------------------------------
__global__ void k_init(int n) {
    int i = blockIdx.x * blockDim.x + threadIdx.x;
    if (i < n) { g_deg[i] = 1; g_fill[i] = 0; }
}

__global__ void k_count_deg(const void* __restrict__ ei, int E) {
    int i = blockIdx.x * blockDim.x + threadIdx.x;
    if (i < E) {
        int d = edge_at(ei, (size_t)E + i);
        if ((unsigned)d < (unsigned)N_NODES) atomicAdd(&g_deg[d], 1);
    }
}

__global__ void k_dinv(int n) {
    int i = blockIdx.x * blockDim.x + threadIdx.x;
    if (i < n) g_dinv[i] = rsqrtf((float)g_deg[i]);
}

// ---------------------------------------------------------------------------
// exclusive scan of g_deg -> g_rowptr
// ---------------------------------------------------------------------------
__device__ __forceinline__ int warp_incl_scan(int v) {
#pragma unroll
    for (int o = 1; o < 32; o <<= 1) {
        int t = __shfl_up_sync(0xffffffffu, v, o);
        if ((threadIdx.x & 31) >= o) v += t;
    }
    return v;
}

__global__ void k_scan_blocks(const int* __restrict__ in, int* __restrict__ out,
                              int* __restrict__ bsums, int n) {
    __shared__ int wsum[8];
    int i = blockIdx.x * 256 + threadIdx.x;
    int v = (i < n) ? in[i] : 0;
    int inc = warp_incl_scan(v);
    int lane = threadIdx.x & 31, w = threadIdx.x >> 5;
    if (lane == 31) wsum[w] = inc;
    __syncthreads();
    if (w == 0) {
        int s = (lane < 8) ? wsum[lane] : 0;
        s = warp_incl_scan(s);
        if (lane < 8) wsum[lane] = s;
    }
    __syncthreads();
    int off = (w > 0) ? wsum[w - 1] : 0;
    if (i < n) out[i] = off + inc - v;
    if (threadIdx.x == 255) bsums[blockIdx.x] = off + inc;
}

__global__ void k_scan_sums(int* __restrict__ bsums, int nb, int* __restrict__ total_out) {
    __shared__ int wsum[8];
    int v = (threadIdx.x < nb) ? bsums[threadIdx.x] : 0;
    int inc = warp_incl_scan(v);
    int lane = threadIdx.x & 31, w = threadIdx.x >> 5;
    if (lane == 31) wsum[w] = inc;
    __syncthreads();
    if (w == 0) {
        int s = (lane < 8) ? wsum[lane] : 0;
        s = warp_incl_scan(s);
        if (lane < 8) wsum[lane] = s;
    }
    __syncthreads();
    int off = (w > 0) ? wsum[w - 1] : 0;
    if (threadIdx.x < nb) bsums[threadIdx.x] = off + inc - v;
    if (threadIdx.x == 255) *total_out = off + inc;
}

__global__ void k_scan_add(int* __restrict__ out, const int* __restrict__ bsums, int n) {
    int i = blockIdx.x * 256 + threadIdx.x;
    if (i < n) out[i] += bsums[blockIdx.x];
}

// ---------------------------------------------------------------------------
// CSR fill
// ---------------------------------------------------------------------------
__global__ void k_fill_csr(const void* __restrict__ ei, int E, int n) {
    int i = blockIdx.x * blockDim.x + threadIdx.x;
    int total = E + n;
    if (i >= total) return;
    int s, d;
    if (i < E) {
        s = edge_at(ei, i);
        d = edge_at(ei, (size_t)E + i);
        if ((unsigned)s >= (unsigned)n || (unsigned)d >= (unsigned)n) return;
    } else {
        s = d = i - E;
    }
    int pos = atomicAdd(&g_fill[d], 1);
    g_csr[g_rowptr[d] + pos] = s;
}

// ---------------------------------------------------------------------------
// hi/lo bf16 split conversions
// ---------------------------------------------------------------------------
__device__ __forceinline__ void split_bf16(float v, __nv_bfloat16& h, __nv_bfloat16& l) {
    h = __float2bfloat16(v);
    l = __float2bfloat16(v - __bfloat162float(h));
}

__global__ void k_conv_x(const float* __restrict__ x, int total) {
    int i = blockIdx.x * blockDim.x + threadIdx.x;
    if (i < total) {
        __nv_bfloat16 h, l;
        split_bf16(x[i], h, l);
        g_xhi[i] = h; g_xlo[i] = l;
    }
}

__global__ void k_conv_w1(const float* __restrict__ W1) {
    int i = blockIdx.x * blockDim.x + threadIdx.x;
    if (i < K1 * N1P) {
        int k = i / N1P, n = i % N1P;
        float v = (n < F_HID) ? W1[k * F_HID + n] : 0.f;
        __nv_bfloat16 h, l;
        split_bf16(v, h, l);
        g_w1hi[i] = h; g_w1lo[i] = l;
    }
}

__global__ void k_conv_w2(const float* __restrict__ W2, int N2real) {
    int i = blockIdx.x * blockDim.x + threadIdx.x;
    if (i < K2P * N2P) {
        int k = i / N2P, n = i % N2P;
        float v = (k < F_HID && n < N2real) ? W2[k * N2real + n] : 0.f;
        __nv_bfloat16 h, l;
        split_bf16(v, h, l);
        g_w2hi[i] = h; g_w2lo[i] = l;
    }
}

// ---------------------------------------------------------------------------
// tensor-core GEMM: C[M,Nreal] = A[M,K](hi+lo) * B[K,Nphys](hi+lo) (+bias)
// ---------------------------------------------------------------------------
__device__ __forceinline__ void cp16(void* dst, const void* src) {
    unsigned d = (unsigned)__cvta_generic_to_shared(dst);
    asm volatile("cp.async.cg.shared.global [%0], [%1], 16;\n" :: "r"(d), "l"(src));
}

__device__ __forceinline__ void ldmA(uint32_t* a, const __nv_bfloat16* p) {
    unsigned addr = (unsigned)__cvta_generic_to_shared(p);
    asm volatile("ldmatrix.sync.aligned.m8n8.x4.shared.b16 {%0,%1,%2,%3}, [%4];"
                 : "=r"(a[0]), "=r"(a[1]), "=r"(a[2]), "=r"(a[3]) : "r"(addr));
}

__device__ __forceinline__ void ldmB(uint32_t* b, const __nv_bfloat16* p) {
    unsigned addr = (unsigned)__cvta_generic_to_shared(p);
    asm volatile("ldmatrix.sync.aligned.m8n8.x2.trans.shared.b16 {%0,%1}, [%2];"
                 : "=r"(b[0]), "=r"(b[1]) : "r"(addr));
}

__device__ __forceinline__ void mma_bf16(float* c, const uint32_t* a, const uint32_t* b) {
    asm volatile("mma.sync.aligned.m16n8k16.row.col.f32.bf16.bf16.f32 "
                 "{%0,%1,%2,%3}, {%4,%5,%6,%7}, {%8,%9}, {%0,%1,%2,%3};"
                 : "+f"(c[0]), "+f"(c[1]), "+f"(c[2]), "+f"(c[3])
                 : "r"(a[0]), "r"(a[1]), "r"(a[2]), "r"(a[3]), "r"(b[0]), "r"(b[1]));
}

template <bool BIAS>
__global__ __launch_bounds__(256, 1) void k_mma_gemm(
    const __nv_bfloat16* __restrict__ Ahi, const __nv_bfloat16* __restrict__ Alo,
    const __nv_bfloat16* __restrict__ Bhi, const __nv_bfloat16* __restrict__ Blo,
    const float* __restrict__ bias, float* __restrict__ C,
    int M, int Nreal, int Nphys, int K) {
    extern __shared__ __nv_bfloat16 smem[];
    __nv_bfloat16* sAh = smem;
    __nv_bfloat16* sAl = sAh + 2 * BM * AP;
    __nv_bfloat16* sBh = sAl + 2 * BM * AP;
    __nv_bfloat16* sBl = sBh + 2 * BK * BP;

    int tid = threadIdx.x;
    int lane = tid & 31, wid = tid >> 5;
    int wm = (wid >> 2) * 64;
    int wn = (wid & 3) * 32;
    int bm = blockIdx.y * BM, bn = blockIdx.x * BN;

    float acc[4][4][4];
#pragma unroll
    for (int i = 0; i < 4; i++)
#pragma unroll
        for (int j = 0; j < 4; j++)
#pragma unroll
            for (int k = 0; k < 4; k++) acc[i][j][k] = 0.f;

    const int nk = K / BK;

    auto load_stage = [&](int st, int kt) {
        __nv_bfloat16* ah = sAh + st * BM * AP;
        __nv_bfloat16* al = sAl + st * BM * AP;
        __nv_bfloat16* bh = sBh + st * BK * BP;
        __nv_bfloat16* bl = sBl + st * BK * BP;
#pragma unroll
        for (int i = 0; i < 2; i++) {
            int q = tid + i * 256;
            int r = q >> 2, c = q & 3;
            size_t goff = (size_t)(bm + r) * K + kt * BK + c * 8;
            cp16(ah + r * AP + c * 8, Ahi + goff);
            cp16(al + r * AP + c * 8, Alo + goff);
        }
#pragma unroll
        for (int i = 0; i < 2; i++) {
            int q = tid + i * 256;
            int r = q >> 4, c = q & 15;
            size_t goff = (size_t)(kt * BK + r) * Nphys + bn + c * 8;
            cp16(bh + r * BP + c * 8, Bhi + goff);
            cp16(bl + r * BP + c * 8, Blo + goff);
        }
        asm volatile("cp.async.commit_group;\n");
    };

    load_stage(0, 0);

    for (int kt = 0; kt < nk; kt++) {
        if (kt + 1 < nk) {
            load_stage((kt + 1) & 1, kt + 1);
            asm volatile("cp.async.wait_group 1;\n");
        } else {
            asm volatile("cp.async.wait_group 0;\n");
        }
        __syncthreads();

        int st = kt & 1;
        const __nv_bfloat16* ah = sAh + st * BM * AP;
        const __nv_bfloat16* al = sAl + st * BM * AP;
        const __nv_bfloat16* bh = sBh + st * BK * BP;
        const __nv_bfloat16* bl = sBl + st * BK * BP;

#pragma unroll
        for (int ks = 0; ks < 2; ks++) {
            uint32_t Ah[4][4], Al[4][4], Bh[4][2], Bl[4][2];
            int arow = (lane & 15), ahalf = (lane >> 4);
#pragma unroll
            for (int mt = 0; mt < 4; mt++) {
                const __nv_bfloat16* pa =
                    ah + (size_t)(wm + mt * 16 + arow) * AP + ks * 16 + ahalf * 8;
                const __nv_bfloat16* pl =
                    al + (size_t)(wm + mt * 16 + arow) * AP + ks * 16 + ahalf * 8;
                ldmA(Ah[mt], pa);
                ldmA(Al[mt], pl);
            }
#pragma unroll
            for (int nt = 0; nt < 4; nt++) {
                const __nv_bfloat16* pb =
                    bh + (size_t)(ks * 16 + (lane & 15)) * BP + wn + nt * 8;
                const __nv_bfloat16* ql =
                    bl + (size_t)(ks * 16 + (lane & 15)) * BP + wn + nt * 8;
                ldmB(Bh[nt], pb);
                ldmB(Bl[nt], ql);
            }
#pragma unroll
            for (int mt = 0; mt < 4; mt++)
#pragma unroll
                for (int nt = 0; nt < 4; nt++) {
                    mma_bf16(acc[mt][nt], Ah[mt], Bh[nt]);
                    mma_bf16(acc[mt][nt], Ah[mt], Bl[nt]);
                    mma_bf16(acc[mt][nt], Al[mt], Bh[nt]);
                }
        }
        __syncthreads();
    }

#pragma unroll
    for (int mt = 0; mt < 4; mt++) {
#pragma unroll
        for (int nt = 0; nt < 4; nt++) {
#pragma unroll
            for (int i = 0; i < 4; i++) {
                int row = bm + wm + mt * 16 + (lane >> 2) + (i >> 1) * 8;
                int col = bn + wn + nt * 8 + (lane & 3) * 2 + (i & 1);
                if (row < M && col < Nreal) {
                    float v = acc[mt][nt][i];
                    if (BIAS) v += bias[col];
                    C[(size_t)row * Nreal + col] = v;
                }
            }
        }
    }
}

// ---------------------------------------------------------------------------
// CSR aggregation over F=400 features, one block (128 thr) per node.
// float4 path, x4 unrolled edge loop (4 independent LDG.128 in flight).
// ---------------------------------------------------------------------------
template <bool RELU, bool BF16OUT>
__global__ __launch_bounds__(128) void k_aggregate(
    const float* __restrict__ H, const float* __restrict__ bias,
    float* __restrict__ out, __nv_bfloat16* __restrict__ outHi,
    __nv_bfloat16* __restrict__ outLo, int node0) {
    __shared__ int   s_idx[128];
    __shared__ float s_w[128];

    int node = blockIdx.x + node0;
    int tid = threadIdx.x;
    int start = g_rowptr[node], end = g_rowptr[node + 1];
    float dd = g_dinv[node];

    float4 acc = make_float4(0.f, 0.f, 0.f, 0.f);
    const bool active = tid < (F_HID / 4);   // 100 float4 lanes

    for (int base = start; base < end; base += 128) {
        int cnt = min(128, end - base);
        if (tid < cnt) {
            int s = g_csr[base + tid];
            s_idx[tid] = s;
            s_w[tid] = g_dinv[s] * dd;
        }
        __syncthreads();
        if (active) {
            int j = 0;
            for (; j + 4 <= cnt; j += 4) {
                const float4* p0 = (const float4*)(H + (size_t)s_idx[j + 0] * F_HID);
                const float4* p1 = (const float4*)(H + (size_t)s_idx[j + 1] * F_HID);
                const float4* p2 = (const float4*)(H + (size_t)s_idx[j + 2] * F_HID);
                const float4* p3 = (const float4*)(H + (size_t)s_idx[j + 3] * F_HID);
                float4 v0 = p0[tid], v1 = p1[tid], v2 = p2[tid], v3 = p3[tid];
                float w0 = s_w[j + 0], w1 = s_w[j + 1];
                float w2 = s_w[j + 2], w3 = s_w[j + 3];
                acc.x += v0.x * w0; acc.y += v0.y * w0;
                acc.z += v0.z * w0; acc.w += v0.w * w0;
                acc.x += v1.x * w1; acc.y += v1.y * w1;
                acc.z += v1.z * w1; acc.w += v1.w * w1;
                acc.x += v2.x * w2; acc.y += v2.y * w2;
                acc.z += v2.z * w2; acc.w += v2.w * w2;
                acc.x += v3.x * w3; acc.y += v3.y * w3;
                acc.z += v3.z * w3; acc.w += v3.w * w3;
            }
            for (; j < cnt; j++) {
                const float4* p0 = (const float4*)(H + (size_t)s_idx[j] * F_HID);
                float w0 = s_w[j];
                float4 v0 = p0[tid];
                acc.x += v0.x * w0; acc.y += v0.y * w0;
                acc.z += v0.z * w0; acc.w += v0.w * w0;
            }
        }
        __syncthreads();
    }

    if (active) {
        if (bias) {
            float4 b = ((const float4*)bias)[tid];
            acc.x += b.x; acc.y += b.y; acc.z += b.z; acc.w += b.w;
        }
        if (RELU) {
            acc.x = fmaxf(acc.x, 0.f); acc.y = fmaxf(acc.y, 0.f);
            acc.z = fmaxf(acc.z, 0.f); acc.w = fmaxf(acc.w, 0.f);
        }
        if (BF16OUT) {
            float v[4] = {acc.x, acc.y, acc.z, acc.w};
            __nv_bfloat16 hh[4], ll[4];
#pragma unroll
            for (int k = 0; k < 4; k++) split_bf16(v[k], hh[k], ll[k]);
            *(uint2*)(outHi + (size_t)node * K2P + tid * 4) = *(uint2*)hh;
            *(uint2*)(outLo + (size_t)node * K2P + tid * 4) = *(uint2*)ll;
        } else {
            ((float4*)(out + (size_t)node * F_HID))[tid] = acc;
        }
    }
}

// ---------------------------------------------------------------------------
// launch
// ---------------------------------------------------------------------------
extern "C" void kernel_launch(void* const* d_in, const int* in_sizes, int n_in,
                              void* d_out, int out_size) {
    const float* x  = (const float*)d_in[0];
    const void*  ei = d_in[1];
    const float* W1 = (const float*)d_in[2];
    const float* b1 = (const float*)d_in[3];
    const float* W2 = (const float*)d_in[4];
    const float* b2 = (const float*)d_in[5];
    float* out = (float*)d_out;

    const int N = N_NODES;
    const int E = in_sizes[1] / 2;
    const int H2 = in_sizes[5];                       // 800

    float *h1, *agg1;
    __nv_bfloat16 *xhi, *xlo, *a2hi, *a2lo, *w1hi, *w1lo, *w2hi, *w2lo;
    int *deg, *rowptr, *bsums;
    cudaGetSymbolAddress((void**)&h1, g_h1);
    cudaGetSymbolAddress((void**)&agg1, g_agg1);
    cudaGetSymbolAddress((void**)&xhi, g_xhi);
    cudaGetSymbolAddress((void**)&xlo, g_xlo);
    cudaGetSymbolAddress((void**)&a2hi, g_a2hi);
    cudaGetSymbolAddress((void**)&a2lo, g_a2lo);
    cudaGetSymbolAddress((void**)&w1hi, g_w1hi);
    cudaGetSymbolAddress((void**)&w1lo, g_w1lo);
    cudaGetSymbolAddress((void**)&w2hi, g_w2hi);
    cudaGetSymbolAddress((void**)&w2lo, g_w2lo);
    cudaGetSymbolAddress((void**)&deg, g_deg);
    cudaGetSymbolAddress((void**)&rowptr, g_rowptr);
    cudaGetSymbolAddress((void**)&bsums, g_bsums);

    static int inited = 0;
    static cudaStream_t s2;
    static cudaEvent_t evRoot, evCsr, evA, evG2;
    if (!inited) {
        cudaFuncSetAttribute(k_mma_gemm<false>,
                             cudaFuncAttributeMaxDynamicSharedMemorySize, GEMM_SMEM);
        cudaFuncSetAttribute(k_mma_gemm<true>,
                             cudaFuncAttributeMaxDynamicSharedMemorySize, GEMM_SMEM);
        cudaStreamCreateWithFlags(&s2, cudaStreamNonBlocking);
        cudaEventCreateWithFlags(&evRoot, cudaEventDisableTiming);
        cudaEventCreateWithFlags(&evCsr, cudaEventDisableTiming);
        cudaEventCreateWithFlags(&evA, cudaEventDisableTiming);
        cudaEventCreateWithFlags(&evG2, cudaEventDisableTiming);
        inited = 1;
    }

    // ---- fork ---------------------------------------------------------------
    cudaEventRecord(evRoot, 0);
    cudaStreamWaitEvent(s2, evRoot, 0);

    // main: conversions needed by GEMM1
    k_conv_x<<<(N * K1 + 255) / 256, 256>>>(x, N * K1);
    k_conv_w1<<<(K1 * N1P + 255) / 256, 256>>>(W1);

    // s2: W2 conversion (GEMM2-only) + full CSR build chain
    k_conv_w2<<<(K2P * N2P + 255) / 256, 256, 0, s2>>>(W2, H2);
    k_detect<<<1, 32, 0, s2>>>(ei);
    k_init<<<(N + 255) / 256, 256, 0, s2>>>(N);
    k_count_deg<<<(E + 255) / 256, 256, 0, s2>>>(ei, E);
    k_dinv<<<(N + 255) / 256, 256, 0, s2>>>(N);
    int nb = (N + 255) / 256;
    k_scan_blocks<<<nb, 256, 0, s2>>>(deg, rowptr, bsums, N);
    k_scan_sums<<<1, 256, 0, s2>>>(bsums, nb, rowptr + N);
    k_scan_add<<<nb, 256, 0, s2>>>(rowptr, bsums, N);
    k_fill_csr<<<(E + N + 255) / 256, 256, 0, s2>>>(ei, E, N);
    cudaEventRecord(evCsr, s2);

    // main: GEMM1 (overlaps CSR chain)
    {
        dim3 grid(N1P / BN, (N + BM - 1) / BM);
        k_mma_gemm<false><<<grid, 256, GEMM_SMEM>>>(
            xhi, xlo, w1hi, w1lo, nullptr, h1, N, F_HID, N1P, K1);
    }

    // ---- join: aggregations need CSR ---------------------------------------
    cudaStreamWaitEvent(0, evCsr, 0);

    // agg1 (full — random gather needs all h1 rows)
    k_aggregate<true, false><<<N, 128>>>(h1, b1, agg1, nullptr, nullptr, 0);

    // agg2 chunk0 -> event -> GEMM2 chunk0 on s2 (overlaps agg2 chunk1)
    k_aggregate<false, true><<<SPLIT_R, 128>>>(agg1, nullptr, nullptr, a2hi, a2lo, 0);
    cudaEventRecord(evA, 0);
    cudaStreamWaitEvent(s2, evA, 0);
    {
        dim3 grid(N2P / BN, SPLIT_R / BM);            // 7 x 196
        k_mma_gemm<true><<<grid, 256, GEMM_SMEM, s2>>>(
            a2hi, a2lo, w2hi, w2lo, b2, out, SPLIT_R, H2, N2P, K2P);
    }
    cudaEventRecord(evG2, s2);

    // main: agg2 chunk1, then GEMM2 chunk1
    k_aggregate<false, true><<<N - SPLIT_R, 128>>>(agg1, nullptr, nullptr,
                                                   a2hi, a2lo, SPLIT_R);
    {
        int mrem = N - SPLIT_R;                       // 24912
        dim3 grid(N2P / BN, (mrem + BM - 1) / BM);    // 7 x 195
        k_mma_gemm<true><<<grid, 256, GEMM_SMEM>>>(
            a2hi + (size_t)SPLIT_R * K2P, a2lo + (size_t)SPLIT_R * K2P,
            w2hi, w2lo, b2, out + (size_t)SPLIT_R * H2, mrem, H2, N2P, K2P);
    }
    // join s2 branch back into origin stream
    cudaStreamWaitEvent(0, evG2, 0);
}

// round 10
// speedup vs baseline: 2.0536x; 1.0536x over previous
#include <cuda_runtime.h>
#include <cuda_bf16.h>
#include <cuda_fp16.h>
#include <stdint.h>

// ---------------------------------------------------------------------------
// GCN 2-layer:  out = Anorm @ relu(Anorm @ (x@W1) + b1) @ W2 + b2
// Layer 2 via linearity: (Anorm @ h1relu) @ W2 + b2.
// GEMMs: mma.sync bf16 hi/lo Markidis (tcgen05 unavailable: harness compiles
// compute_103 PTX which rejects tcgen05).
// R9 (= R7 resubmit after infra failure): fp16 feature pipeline for the
// aggregations — halves L2 gather traffic, fp32 accumulation.
// ---------------------------------------------------------------------------

#define N_NODES 50000
#define M_PAD   50048
#define MAX_E   1600000
#define MAX_CSR (MAX_E + N_NODES)
#define F_HID   400
#define K1      512
#define N1P     512
#define K2P     416
#define N2P     896
#define SPLIT_R 25088          // agg2/GEMM2 chunk boundary (196 * 128)

// GEMM tiling
#define BM 128
#define BN 128
#define BK 32
#define AP 40
#define BP 136
#define GEMM_SMEM ((2*BM*AP + 2*BK*BP) * 2 * 2)   // 75776 bytes

// ------------------------------- scratch -----------------------------------
__device__ __half g_h1h[(size_t)N_NODES * F_HID];    // x@W1 (fp16)
__device__ __half g_agg1h[(size_t)N_NODES * F_HID];  // relu(agg(h1)+b1) (fp16)
__device__ __nv_bfloat16 g_xhi[(size_t)M_PAD * K1];
__device__ __nv_bfloat16 g_xlo[(size_t)M_PAD * K1];
__device__ __nv_bfloat16 g_a2hi[(size_t)M_PAD * K2P];
__device__ __nv_bfloat16 g_a2lo[(size_t)M_PAD * K2P];
__device__ __nv_bfloat16 g_w1hi[K1 * N1P];
__device__ __nv_bfloat16 g_w1lo[K1 * N1P];
__device__ __nv_bfloat16 g_w2hi[K2P * N2P];
__device__ __nv_bfloat16 g_w2lo[K2P * N2P];
__device__ float g_dinv[N_NODES];
__device__ int   g_deg[N_NODES];
__device__ int   g_fill[N_NODES];
__device__ int   g_rowptr[N_NODES + 1];
__device__ int   g_csr[MAX_CSR];
__device__ int   g_bsums[512];
__device__ int   g_is64;

// ---------------------------------------------------------------------------
// edge dtype detection (int32 vs int64 delivery)
// ---------------------------------------------------------------------------
__global__ void k_detect(const void* __restrict__ ei) {
    if (threadIdx.x == 0 && blockIdx.x == 0) {
        const long long* p = (const long long*)ei;
        int ok64 = 1;
#pragma unroll
        for (int i = 0; i < 16; i++) {
            long long v = p[i];
            if (v < 0 || v >= N_NODES) ok64 = 0;
        }
        g_is64 = ok64;
    }
}

__device__ __forceinline__ int edge_at(const void* ei, size_t idx) {
    if (g_is64) return (int)((const long long*)ei)[idx];
    return ((const int*)ei)[idx];
}

// ---------------------------------------------------------------------------
// degree / dinv
// ---------------------------------------------------------------------------
__global__ void k_init(int n) {
    int i = blockIdx.x * blockDim.x + threadIdx.x;
    if (i < n) { g_deg[i] = 1; g_fill[i] = 0; }
}

__global__ void k_count_deg(const void* __restrict__ ei, int E) {
    int i = blockIdx.x * blockDim.x + threadIdx.x;
    if (i < E) {
        int d = edge_at(ei, (size_t)E + i);
        if ((unsigned)d < (unsigned)N_NODES) atomicAdd(&g_deg[d], 1);
    }
}

__global__ void k_dinv(int n) {
    int i = blockIdx.x * blockDim.x + threadIdx.x;
    if (i < n) g_dinv[i] = rsqrtf((float)g_deg[i]);
}

// ---------------------------------------------------------------------------
// exclusive scan of g_deg -> g_rowptr
// ---------------------------------------------------------------------------
__device__ __forceinline__ int warp_incl_scan(int v) {
#pragma unroll
    for (int o = 1; o < 32; o <<= 1) {
        int t = __shfl_up_sync(0xffffffffu, v, o);
        if ((threadIdx.x & 31) >= o) v += t;
    }
    return v;
}

__global__ void k_scan_blocks(const int* __restrict__ in, int* __restrict__ out,
                              int* __restrict__ bsums, int n) {
    __shared__ int wsum[8];
    int i = blockIdx.x * 256 + threadIdx.x;
    int v = (i < n) ? in[i] : 0;
    int inc = warp_incl_scan(v);
    int lane = threadIdx.x & 31, w = threadIdx.x >> 5;
    if (lane == 31) wsum[w] = inc;
    __syncthreads();
    if (w == 0) {
        int s = (lane < 8) ? wsum[lane] : 0;
        s = warp_incl_scan(s);
        if (lane < 8) wsum[lane] = s;
    }
    __syncthreads();
    int off = (w > 0) ? wsum[w - 1] : 0;
    if (i < n) out[i] = off + inc - v;
    if (threadIdx.x == 255) bsums[blockIdx.x] = off + inc;
}

__global__ void k_scan_sums(int* __restrict__ bsums, int nb, int* __restrict__ total_out) {
    __shared__ int wsum[8];
    int v = (threadIdx.x < nb) ? bsums[threadIdx.x] : 0;
    int inc = warp_incl_scan(v);
    int lane = threadIdx.x & 31, w = threadIdx.x >> 5;
    if (lane == 31) wsum[w] = inc;
    __syncthreads();
    if (w == 0) {
        int s = (lane < 8) ? wsum[lane] : 0;
        s = warp_incl_scan(s);
        if (lane < 8) wsum[lane] = s;
    }
    __syncthreads();
    int off = (w > 0) ? wsum[w - 1] : 0;
    if (threadIdx.x < nb) bsums[threadIdx.x] = off + inc - v;
    if (threadIdx.x == 255) *total_out = off + inc;
}

__global__ void k_scan_add(int* __restrict__ out, const int* __restrict__ bsums, int n) {
    int i = blockIdx.x * 256 + threadIdx.x;
    if (i < n) out[i] += bsums[blockIdx.x];
}

// ---------------------------------------------------------------------------
// CSR fill
// ---------------------------------------------------------------------------
__global__ void k_fill_csr(const void* __restrict__ ei, int E, int n) {
    int i = blockIdx.x * blockDim.x + threadIdx.x;
    int total = E + n;
    if (i >= total) return;
    int s, d;
    if (i < E) {
        s = edge_at(ei, i);
        d = edge_at(ei, (size_t)E + i);
        if ((unsigned)s >= (unsigned)n || (unsigned)d >= (unsigned)n) return;
    } else {
        s = d = i - E;
    }
    int pos = atomicAdd(&g_fill[d], 1);
    g_csr[g_rowptr[d] + pos] = s;
}

// ---------------------------------------------------------------------------
// hi/lo bf16 split conversions
// ---------------------------------------------------------------------------
__device__ __forceinline__ void split_bf16(float v, __nv_bfloat16& h, __nv_bfloat16& l) {
    h = __float2bfloat16(v);
    l = __float2bfloat16(v - __bfloat162float(h));
}

__global__ void k_conv_x(const float* __restrict__ x, int total) {
    int i = blockIdx.x * blockDim.x + threadIdx.x;
    if (i < total) {
        __nv_bfloat16 h, l;
        split_bf16(x[i], h, l);
        g_xhi[i] = h; g_xlo[i] = l;
    }
}

__global__ void k_conv_w1(const float* __restrict__ W1) {
    int i = blockIdx.x * blockDim.x + threadIdx.x;
    if (i < K1 * N1P) {
        int k = i / N1P, n = i % N1P;
        float v = (n < F_HID) ? W1[k * F_HID + n] : 0.f;
        __nv_bfloat16 h, l;
        split_bf16(v, h, l);
        g_w1hi[i] = h; g_w1lo[i] = l;
    }
}

__global__ void k_conv_w2(const float* __restrict__ W2, int N2real) {
    int i = blockIdx.x * blockDim.x + threadIdx.x;
    if (i < K2P * N2P) {
        int k = i / N2P, n = i % N2P;
        float v = (k < F_HID && n < N2real) ? W2[k * N2real + n] : 0.f;
        __nv_bfloat16 h, l;
        split_bf16(v, h, l);
        g_w2hi[i] = h; g_w2lo[i] = l;
    }
}

// ---------------------------------------------------------------------------
// tensor-core GEMM: C = A(hi+lo) * B(hi+lo) (+bias).  HOUT: fp16 output.
// ---------------------------------------------------------------------------
__device__ __forceinline__ void cp16(void* dst, const void* src) {
    unsigned d = (unsigned)__cvta_generic_to_shared(dst);
    asm volatile("cp.async.cg.shared.global [%0], [%1], 16;\n" :: "r"(d), "l"(src));
}

__device__ __forceinline__ void ldmA(uint32_t* a, const __nv_bfloat16* p) {
    unsigned addr = (unsigned)__cvta_generic_to_shared(p);
    asm volatile("ldmatrix.sync.aligned.m8n8.x4.shared.b16 {%0,%1,%2,%3}, [%4];"
                 : "=r"(a[0]), "=r"(a[1]), "=r"(a[2]), "=r"(a[3]) : "r"(addr));
}

__device__ __forceinline__ void ldmB(uint32_t* b, const __nv_bfloat16* p) {
    unsigned addr = (unsigned)__cvta_generic_to_shared(p);
    asm volatile("ldmatrix.sync.aligned.m8n8.x2.trans.shared.b16 {%0,%1}, [%2];"
                 : "=r"(b[0]), "=r"(b[1]) : "r"(addr));
}

__device__ __forceinline__ void mma_bf16(float* c, const uint32_t* a, const uint32_t* b) {
    asm volatile("mma.sync.aligned.m16n8k16.row.col.f32.bf16.bf16.f32 "
                 "{%0,%1,%2,%3}, {%4,%5,%6,%7}, {%8,%9}, {%0,%1,%2,%3};"
                 : "+f"(c[0]), "+f"(c[1]), "+f"(c[2]), "+f"(c[3])
                 : "r"(a[0]), "r"(a[1]), "r"(a[2]), "r"(a[3]), "r"(b[0]), "r"(b[1]));
}

template <bool BIAS, bool HOUT>
__global__ __launch_bounds__(256, 1) void k_mma_gemm(
    const __nv_bfloat16* __restrict__ Ahi, const __nv_bfloat16* __restrict__ Alo,
    const __nv_bfloat16* __restrict__ Bhi, const __nv_bfloat16* __restrict__ Blo,
    const float* __restrict__ bias, float* __restrict__ C, __half* __restrict__ Ch,
    int M, int Nreal, int Nphys, int K) {
    extern __shared__ __nv_bfloat16 smem[];
    __nv_bfloat16* sAh = smem;
    __nv_bfloat16* sAl = sAh + 2 * BM * AP;
    __nv_bfloat16* sBh = sAl + 2 * BM * AP;
    __nv_bfloat16* sBl = sBh + 2 * BK * BP;

    int tid = threadIdx.x;
    int lane = tid & 31, wid = tid >> 5;
    int wm = (wid >> 2) * 64;
    int wn = (wid & 3) * 32;
    int bm = blockIdx.y * BM, bn = blockIdx.x * BN;

    float acc[4][4][4];
#pragma unroll
    for (int i = 0; i < 4; i++)
#pragma unroll
        for (int j = 0; j < 4; j++)
#pragma unroll
            for (int k = 0; k < 4; k++) acc[i][j][k] = 0.f;

    const int nk = K / BK;

    auto load_stage = [&](int st, int kt) {
        __nv_bfloat16* ah = sAh + st * BM * AP;
        __nv_bfloat16* al = sAl + st * BM * AP;
        __nv_bfloat16* bh = sBh + st * BK * BP;
        __nv_bfloat16* bl = sBl + st * BK * BP;
#pragma unroll
        for (int i = 0; i < 2; i++) {
            int q = tid + i * 256;
            int r = q >> 2, c = q & 3;
            size_t goff = (size_t)(bm + r) * K + kt * BK + c * 8;
            cp16(ah + r * AP + c * 8, Ahi + goff);
            cp16(al + r * AP + c * 8, Alo + goff);
        }
#pragma unroll
        for (int i = 0; i < 2; i++) {
            int q = tid + i * 256;
            int r = q >> 4, c = q & 15;
            size_t goff = (size_t)(kt * BK + r) * Nphys + bn + c * 8;
            cp16(bh + r * BP + c * 8, Bhi + goff);
            cp16(bl + r * BP + c * 8, Blo + goff);
        }
        asm volatile("cp.async.commit_group;\n");
    };

    load_stage(0, 0);

    for (int kt = 0; kt < nk; kt++) {
        if (kt + 1 < nk) {
            load_stage((kt + 1) & 1, kt + 1);
            asm volatile("cp.async.wait_group 1;\n");
        } else {
            asm volatile("cp.async.wait_group 0;\n");
        }
        __syncthreads();

        int st = kt & 1;
        const __nv_bfloat16* ah = sAh + st * BM * AP;
        const __nv_bfloat16* al = sAl + st * BM * AP;
        const __nv_bfloat16* bh = sBh + st * BK * BP;
        const __nv_bfloat16* bl = sBl + st * BK * BP;

#pragma unroll
        for (int ks = 0; ks < 2; ks++) {
            uint32_t Ah[4][4], Al[4][4], Bh[4][2], Bl[4][2];
            int arow = (lane & 15), ahalf = (lane >> 4);
#pragma unroll
            for (int mt = 0; mt < 4; mt++) {
                const __nv_bfloat16* pa =
                    ah + (size_t)(wm + mt * 16 + arow) * AP + ks * 16 + ahalf * 8;
                const __nv_bfloat16* pl =
                    al + (size_t)(wm + mt * 16 + arow) * AP + ks * 16 + ahalf * 8;
                ldmA(Ah[mt], pa);
                ldmA(Al[mt], pl);
            }
#pragma unroll
            for (int nt = 0; nt < 4; nt++) {
                const __nv_bfloat16* pb =
                    bh + (size_t)(ks * 16 + (lane & 15)) * BP + wn + nt * 8;
                const __nv_bfloat16* ql =
                    bl + (size_t)(ks * 16 + (lane & 15)) * BP + wn + nt * 8;
                ldmB(Bh[nt], pb);
                ldmB(Bl[nt], ql);
            }
#pragma unroll
            for (int mt = 0; mt < 4; mt++)
#pragma unroll
                for (int nt = 0; nt < 4; nt++) {
                    mma_bf16(acc[mt][nt], Ah[mt], Bh[nt]);
                    mma_bf16(acc[mt][nt], Ah[mt], Bl[nt]);
                    mma_bf16(acc[mt][nt], Al[mt], Bh[nt]);
                }
        }
        __syncthreads();
    }

#pragma unroll
    for (int mt = 0; mt < 4; mt++) {
#pragma unroll
        for (int nt = 0; nt < 4; nt++) {
#pragma unroll
            for (int i = 0; i < 4; i++) {
                int row = bm + wm + mt * 16 + (lane >> 2) + (i >> 1) * 8;
                int col = bn + wn + nt * 8 + (lane & 3) * 2 + (i & 1);
                if (row < M && col < Nreal) {
                    float v = acc[mt][nt][i];
                    if (BIAS) v += bias[col];
                    if (HOUT) Ch[(size_t)row * Nreal + col] = __float2half(v);
                    else      C[(size_t)row * Nreal + col] = v;
                }
            }
        }
    }
}

// ---------------------------------------------------------------------------
// CSR aggregation over F=400 fp16 features, one block (128 thr) per node.
// 100 lanes x uint2 (4 halves, LDG.64) per edge; fp32 accumulation.
// ---------------------------------------------------------------------------
template <bool RELU, bool BF16OUT>
__global__ __launch_bounds__(128) void k_aggregate(
    const __half* __restrict__ H, const float* __restrict__ bias,
    __half* __restrict__ outH, __nv_bfloat16* __restrict__ outHi,
    __nv_bfloat16* __restrict__ outLo, int node0) {
    __shared__ int   s_idx[128];
    __shared__ float s_w[128];

    int node = blockIdx.x + node0;
    int tid = threadIdx.x;
    int start = g_rowptr[node], end = g_rowptr[node + 1];
    float dd = g_dinv[node];

    float4 acc = make_float4(0.f, 0.f, 0.f, 0.f);
    const bool active = tid < (F_HID / 4);   // 100 uint2 lanes

    for (int base = start; base < end; base += 128) {
        int cnt = min(128, end - base);
        if (tid < cnt) {
            int s = g_csr[base + tid];
            s_idx[tid] = s;
            s_w[tid] = g_dinv[s] * dd;
        }
        __syncthreads();
        if (active) {
            int j = 0;
            for (; j + 4 <= cnt; j += 4) {
                uint2 u0 = ((const uint2*)(H + (size_t)s_idx[j + 0] * F_HID))[tid];
                uint2 u1 = ((const uint2*)(H + (size_t)s_idx[j + 1] * F_HID))[tid];
                uint2 u2 = ((const uint2*)(H + (size_t)s_idx[j + 2] * F_HID))[tid];
                uint2 u3 = ((const uint2*)(H + (size_t)s_idx[j + 3] * F_HID))[tid];
                float w0 = s_w[j + 0], w1 = s_w[j + 1];
                float w2 = s_w[j + 2], w3 = s_w[j + 3];
                float2 a0 = __half22float2(*(__half2*)&u0.x);
                float2 b0 = __half22float2(*(__half2*)&u0.y);
                float2 a1 = __half22float2(*(__half2*)&u1.x);
                float2 b1 = __half22float2(*(__half2*)&u1.y);
                float2 a2 = __half22float2(*(__half2*)&u2.x);
                float2 b2 = __half22float2(*(__half2*)&u2.y);
                float2 a3 = __half22float2(*(__half2*)&u3.x);
                float2 b3 = __half22float2(*(__half2*)&u3.y);
                acc.x += a0.x * w0; acc.y += a0.y * w0;
                acc.z += b0.x * w0; acc.w += b0.y * w0;
                acc.x += a1.x * w1; acc.y += a1.y * w1;
                acc.z += b1.x * w1; acc.w += b1.y * w1;
                acc.x += a2.x * w2; acc.y += a2.y * w2;
                acc.z += b2.x * w2; acc.w += b2.y * w2;
                acc.x += a3.x * w3; acc.y += a3.y * w3;
                acc.z += b3.x * w3; acc.w += b3.y * w3;
            }
            for (; j < cnt; j++) {
                uint2 u0 = ((const uint2*)(H + (size_t)s_idx[j] * F_HID))[tid];
                float w0 = s_w[j];
                float2 a0 = __half22float2(*(__half2*)&u0.x);
                float2 b0 = __half22float2(*(__half2*)&u0.y);
                acc.x += a0.x * w0; acc.y += a0.y * w0;
                acc.z += b0.x * w0; acc.w += b0.y * w0;
            }
        }
        __syncthreads();
    }

    if (active) {
        if (bias) {
            float4 b = ((const float4*)bias)[tid];
            acc.x += b.x; acc.y += b.y; acc.z += b.z; acc.w += b.w;
        }
        if (RELU) {
            acc.x = fmaxf(acc.x, 0.f); acc.y = fmaxf(acc.y, 0.f);
            acc.z = fmaxf(acc.z, 0.f); acc.w = fmaxf(acc.w, 0.f);
        }
        if (BF16OUT) {
            float v[4] = {acc.x, acc.y, acc.z, acc.w};
            __nv_bfloat16 hh[4], ll[4];
#pragma unroll
            for (int k = 0; k < 4; k++) split_bf16(v[k], hh[k], ll[k]);
            *(uint2*)(outHi + (size_t)node * K2P + tid * 4) = *(uint2*)hh;
            *(uint2*)(outLo + (size_t)node * K2P + tid * 4) = *(uint2*)ll;
        } else {
            __half2 h01 = __floats2half2_rn(acc.x, acc.y);
            __half2 h23 = __floats2half2_rn(acc.z, acc.w);
            uint2 u;
            u.x = *(uint32_t*)&h01; u.y = *(uint32_t*)&h23;
            ((uint2*)(outH + (size_t)node * F_HID))[tid] = u;
        }
    }
}

// ---------------------------------------------------------------------------
// launch
// ---------------------------------------------------------------------------
extern "C" void kernel_launch(void* const* d_in, const int* in_sizes, int n_in,
                              void* d_out, int out_size) {
    const float* x  = (const float*)d_in[0];
    const void*  ei = d_in[1];
    const float* W1 = (const float*)d_in[2];
    const float* b1 = (const float*)d_in[3];
    const float* W2 = (const float*)d_in[4];
    const float* b2 = (const float*)d_in[5];
    float* out = (float*)d_out;

    const int N = N_NODES;
    const int E = in_sizes[1] / 2;
    const int H2 = in_sizes[5];                       // 800

    __half *h1h, *agg1h;
    __nv_bfloat16 *xhi, *xlo, *a2hi, *a2lo, *w1hi, *w1lo, *w2hi, *w2lo;
    int *deg, *rowptr, *bsums;
    cudaGetSymbolAddress((void**)&h1h, g_h1h);
    cudaGetSymbolAddress((void**)&agg1h, g_agg1h);
    cudaGetSymbolAddress((void**)&xhi, g_xhi);
    cudaGetSymbolAddress((void**)&xlo, g_xlo);
    cudaGetSymbolAddress((void**)&a2hi, g_a2hi);
    cudaGetSymbolAddress((void**)&a2lo, g_a2lo);
    cudaGetSymbolAddress((void**)&w1hi, g_w1hi);
    cudaGetSymbolAddress((void**)&w1lo, g_w1lo);
    cudaGetSymbolAddress((void**)&w2hi, g_w2hi);
    cudaGetSymbolAddress((void**)&w2lo, g_w2lo);
    cudaGetSymbolAddress((void**)&deg, g_deg);
    cudaGetSymbolAddress((void**)&rowptr, g_rowptr);
    cudaGetSymbolAddress((void**)&bsums, g_bsums);

    static int inited = 0;
    static cudaStream_t s2;
    static cudaEvent_t evRoot, evCsr, evA, evG2;
    if (!inited) {
        cudaFuncSetAttribute(k_mma_gemm<false, true>,
                             cudaFuncAttributeMaxDynamicSharedMemorySize, GEMM_SMEM);
        cudaFuncSetAttribute(k_mma_gemm<true, false>,
                             cudaFuncAttributeMaxDynamicSharedMemorySize, GEMM_SMEM);
        cudaStreamCreateWithFlags(&s2, cudaStreamNonBlocking);
        cudaEventCreateWithFlags(&evRoot, cudaEventDisableTiming);
        cudaEventCreateWithFlags(&evCsr, cudaEventDisableTiming);
        cudaEventCreateWithFlags(&evA, cudaEventDisableTiming);
        cudaEventCreateWithFlags(&evG2, cudaEventDisableTiming);
        inited = 1;
    }

    // ---- fork ---------------------------------------------------------------
    cudaEventRecord(evRoot, 0);
    cudaStreamWaitEvent(s2, evRoot, 0);

    // main: conversions needed by GEMM1
    k_conv_x<<<(N * K1 + 255) / 256, 256>>>(x, N * K1);
    k_conv_w1<<<(K1 * N1P + 255) / 256, 256>>>(W1);

    // s2: W2 conversion + full CSR build chain (latency-bound, overlaps GEMM1)
    k_conv_w2<<<(K2P * N2P + 255) / 256, 256, 0, s2>>>(W2, H2);
    k_detect<<<1, 32, 0, s2>>>(ei);
    k_init<<<(N + 255) / 256, 256, 0, s2>>>(N);
    k_count_deg<<<(E + 255) / 256, 256, 0, s2>>>(ei, E);
    k_dinv<<<(N + 255) / 256, 256, 0, s2>>>(N);
    int nb = (N + 255) / 256;
    k_scan_blocks<<<nb, 256, 0, s2>>>(deg, rowptr, bsums, N);
    k_scan_sums<<<1, 256, 0, s2>>>(bsums, nb, rowptr + N);
    k_scan_add<<<nb, 256, 0, s2>>>(rowptr, bsums, N);
    k_fill_csr<<<(E + N + 255) / 256, 256, 0, s2>>>(ei, E, N);
    cudaEventRecord(evCsr, s2);

    // main: GEMM1 -> h1 (fp16)
    {
        dim3 grid(N1P / BN, (N + BM - 1) / BM);
        k_mma_gemm<false, true><<<grid, 256, GEMM_SMEM>>>(
            xhi, xlo, w1hi, w1lo, nullptr, nullptr, h1h, N, F_HID, N1P, K1);
    }

    // ---- join: aggregations need CSR ---------------------------------------
    cudaStreamWaitEvent(0, evCsr, 0);

    // agg1: fp16 gather -> fp16 out
    k_aggregate<true, false><<<N, 128>>>(h1h, b1, agg1h, nullptr, nullptr, 0);

    // agg2 chunk0 -> GEMM2 chunk0 on s2 (overlaps agg2 chunk1)
    k_aggregate<false, true><<<SPLIT_R, 128>>>(agg1h, nullptr, nullptr, a2hi, a2lo, 0);
    cudaEventRecord(evA, 0);
    cudaStreamWaitEvent(s2, evA, 0);
    {
        dim3 grid(N2P / BN, SPLIT_R / BM);
        k_mma_gemm<true, false><<<grid, 256, GEMM_SMEM, s2>>>(
            a2hi, a2lo, w2hi, w2lo, b2, out, nullptr, SPLIT_R, H2, N2P, K2P);
    }
    cudaEventRecord(evG2, s2);

    // main: agg2 chunk1, then GEMM2 chunk1
    k_aggregate<false, true><<<N - SPLIT_R, 128>>>(agg1h, nullptr, nullptr,
                                                   a2hi, a2lo, SPLIT_R);
    {
        int mrem = N - SPLIT_R;
        dim3 grid(N2P / BN, (mrem + BM - 1) / BM);
        k_mma_gemm<true, false><<<grid, 256, GEMM_SMEM>>>(
            a2hi + (size_t)SPLIT_R * K2P, a2lo + (size_t)SPLIT_R * K2P,
            w2hi, w2lo, b2, out + (size_t)SPLIT_R * H2, nullptr, mrem, H2, N2P, K2P);
    }
    cudaStreamWaitEvent(0, evG2, 0);
}

// round 11
// speedup vs baseline: 2.3934x; 1.1655x over previous
#include <cuda_runtime.h>
#include <cuda_bf16.h>
#include <cuda_fp16.h>
#include <stdint.h>

// ---------------------------------------------------------------------------
// GCN 2-layer:  out = Anorm @ relu(Anorm @ (x@W1) + b1) @ W2 + b2
// Layer 2 via linearity: (Anorm @ h1relu) @ W2 + b2.
// R10: 2-chain fp16 Markidis GEMM (A = Ah+Al fp16 split, B single fp16):
// C = A·Bh exactly; only error is B's fp16 rounding (~2.8e-4 RMS).
// mma count -33%, stage loads -25% vs 3-chain bf16.
// (tcgen05 unavailable: harness compiles compute_103 PTX which rejects it.)
// ---------------------------------------------------------------------------

#define N_NODES 50000
#define M_PAD   50048
#define MAX_E   1600000
#define MAX_CSR (MAX_E + N_NODES)
#define F_HID   400
#define K1      512
#define N1P     512
#define K2P     416
#define N2P     896
#define SPLIT_R 25088          // agg2/GEMM2 chunk boundary (196 * 128)

// GEMM tiling
#define BM 128
#define BN 128
#define BK 32
#define AP 40                  // smem A row pitch (halves): 80B, conflict-free ldmatrix
#define BP 136                 // smem B row pitch (halves): 272B, conflict-free ldmatrix
#define GEMM_SMEM ((4*BM*AP + 2*BK*BP) * 2)   // 58368 bytes

// ------------------------------- scratch -----------------------------------
__device__ __half g_h1h[(size_t)N_NODES * F_HID];    // x@W1 (fp16)
__device__ __half g_agg1h[(size_t)N_NODES * F_HID];  // relu(agg(h1)+b1) (fp16)
__device__ __half g_xhi[(size_t)M_PAD * K1];
__device__ __half g_xlo[(size_t)M_PAD * K1];
__device__ __half g_a2hi[(size_t)M_PAD * K2P];       // pad cols 400..415 stay 0
__device__ __half g_a2lo[(size_t)M_PAD * K2P];
__device__ __half g_w1h[K1 * N1P];                   // W1 fp16 (single)
__device__ __half g_w2h[K2P * N2P];                  // W2 fp16 (single)
__device__ float g_dinv[N_NODES];
__device__ int   g_deg[N_NODES];
__device__ int   g_fill[N_NODES];
__device__ int   g_rowptr[N_NODES + 1];
__device__ int   g_csr[MAX_CSR];
__device__ int   g_bsums[512];
__device__ int   g_is64;

// ---------------------------------------------------------------------------
// edge dtype detection (int32 vs int64 delivery)
// ---------------------------------------------------------------------------
__global__ void k_detect(const void* __restrict__ ei) {
    if (threadIdx.x == 0 && blockIdx.x == 0) {
        const long long* p = (const long long*)ei;
        int ok64 = 1;
#pragma unroll
        for (int i = 0; i < 16; i++) {
            long long v = p[i];
            if (v < 0 || v >= N_NODES) ok64 = 0;
        }
        g_is64 = ok64;
    }
}

__device__ __forceinline__ int edge_at(const void* ei, size_t idx) {
    if (g_is64) return (int)((const long long*)ei)[idx];
    return ((const int*)ei)[idx];
}

// ---------------------------------------------------------------------------
// degree / dinv
// ---------------------------------------------------------------------------
__global__ void k_init(int n) {
    int i = blockIdx.x * blockDim.x + threadIdx.x;
    if (i < n) { g_deg[i] = 1; g_fill[i] = 0; }
}

__global__ void k_count_deg(const void* __restrict__ ei, int E) {
    int i = blockIdx.x * blockDim.x + threadIdx.x;
    if (i < E) {
        int d = edge_at(ei, (size_t)E + i);
        if ((unsigned)d < (unsigned)N_NODES) atomicAdd(&g_deg[d], 1);
    }
}

__global__ void k_dinv(int n) {
    int i = blockIdx.x * blockDim.x + threadIdx.x;
    if (i < n) g_dinv[i] = rsqrtf((float)g_deg[i]);
}

// ---------------------------------------------------------------------------
// exclusive scan of g_deg -> g_rowptr
// ---------------------------------------------------------------------------
__device__ __forceinline__ int warp_incl_scan(int v) {
#pragma unroll
    for (int o = 1; o < 32; o <<= 1) {
        int t = __shfl_up_sync(0xffffffffu, v, o);
        if ((threadIdx.x & 31) >= o) v += t;
    }
    return v;
}

__global__ void k_scan_blocks(const int* __restrict__ in, int* __restrict__ out,
                              int* __restrict__ bsums, int n) {
    __shared__ int wsum[8];
    int i = blockIdx.x * 256 + threadIdx.x;
    int v = (i < n) ? in[i] : 0;
    int inc = warp_incl_scan(v);
    int lane = threadIdx.x & 31, w = threadIdx.x >> 5;
    if (lane == 31) wsum[w] = inc;
    __syncthreads();
    if (w == 0) {
        int s = (lane < 8) ? wsum[lane] : 0;
        s = warp_incl_scan(s);
        if (lane < 8) wsum[lane] = s;
    }
    __syncthreads();
    int off = (w > 0) ? wsum[w - 1] : 0;
    if (i < n) out[i] = off + inc - v;
    if (threadIdx.x == 255) bsums[blockIdx.x] = off + inc;
}

__global__ void k_scan_sums(int* __restrict__ bsums, int nb, int* __restrict__ total_out) {
    __shared__ int wsum[8];
    int v = (threadIdx.x < nb) ? bsums[threadIdx.x] : 0;
    int inc = warp_incl_scan(v);
    int lane = threadIdx.x & 31, w = threadIdx.x >> 5;
    if (lane == 31) wsum[w] = inc;
    __syncthreads();
    if (w == 0) {
        int s = (lane < 8) ? wsum[lane] : 0;
        s = warp_incl_scan(s);
        if (lane < 8) wsum[lane] = s;
    }
    __syncthreads();
    int off = (w > 0) ? wsum[w - 1] : 0;
    if (threadIdx.x < nb) bsums[threadIdx.x] = off + inc - v;
    if (threadIdx.x == 255) *total_out = off + inc;
}

__global__ void k_scan_add(int* __restrict__ out, const int* __restrict__ bsums, int n) {
    int i = blockIdx.x * 256 + threadIdx.x;
    if (i < n) out[i] += bsums[blockIdx.x];
}

// ---------------------------------------------------------------------------
// CSR fill
// ---------------------------------------------------------------------------
__global__ void k_fill_csr(const void* __restrict__ ei, int E, int n) {
    int i = blockIdx.x * blockDim.x + threadIdx.x;
    int total = E + n;
    if (i >= total) return;
    int s, d;
    if (i < E) {
        s = edge_at(ei, i);
        d = edge_at(ei, (size_t)E + i);
        if ((unsigned)s >= (unsigned)n || (unsigned)d >= (unsigned)n) return;
    } else {
        s = d = i - E;
    }
    int pos = atomicAdd(&g_fill[d], 1);
    g_csr[g_rowptr[d] + pos] = s;
}

// ---------------------------------------------------------------------------
// fp16 hi/lo split conversions
// ---------------------------------------------------------------------------
__device__ __forceinline__ void split_fp16(float v, __half& h, __half& l) {
    h = __float2half(v);
    l = __float2half(v - __half2float(h));
}

__global__ void k_conv_x(const float* __restrict__ x, int total) {
    int i = blockIdx.x * blockDim.x + threadIdx.x;
    if (i < total) {
        __half h, l;
        split_fp16(x[i], h, l);
        g_xhi[i] = h; g_xlo[i] = l;
    }
}

__global__ void k_conv_w1(const float* __restrict__ W1) {
    int i = blockIdx.x * blockDim.x + threadIdx.x;
    if (i < K1 * N1P) {
        int k = i / N1P, n = i % N1P;
        float v = (n < F_HID) ? W1[k * F_HID + n] : 0.f;
        g_w1h[i] = __float2half(v);
    }
}

__global__ void k_conv_w2(const float* __restrict__ W2, int N2real) {
    int i = blockIdx.x * blockDim.x + threadIdx.x;
    if (i < K2P * N2P) {
        int k = i / N2P, n = i % N2P;
        float v = (k < F_HID && n < N2real) ? W2[k * N2real + n] : 0.f;
        g_w2h[i] = __float2half(v);
    }
}

// ---------------------------------------------------------------------------
// tensor-core GEMM:  C = (Ahi+Alo) * Bh (+bias)  — 2-chain fp16 split
// ---------------------------------------------------------------------------
__device__ __forceinline__ void cp16(void* dst, const void* src) {
    unsigned d = (unsigned)__cvta_generic_to_shared(dst);
    asm volatile("cp.async.cg.shared.global [%0], [%1], 16;\n" :: "r"(d), "l"(src));
}

__device__ __forceinline__ void ldmA(uint32_t* a, const __half* p) {
    unsigned addr = (unsigned)__cvta_generic_to_shared(p);
    asm volatile("ldmatrix.sync.aligned.m8n8.x4.shared.b16 {%0,%1,%2,%3}, [%4];"
                 : "=r"(a[0]), "=r"(a[1]), "=r"(a[2]), "=r"(a[3]) : "r"(addr));
}

__device__ __forceinline__ void ldmB(uint32_t* b, const __half* p) {
    unsigned addr = (unsigned)__cvta_generic_to_shared(p);
    asm volatile("ldmatrix.sync.aligned.m8n8.x2.trans.shared.b16 {%0,%1}, [%2];"
                 : "=r"(b[0]), "=r"(b[1]) : "r"(addr));
}

__device__ __forceinline__ void mma_fp16(float* c, const uint32_t* a, const uint32_t* b) {
    asm volatile("mma.sync.aligned.m16n8k16.row.col.f32.f16.f16.f32 "
                 "{%0,%1,%2,%3}, {%4,%5,%6,%7}, {%8,%9}, {%0,%1,%2,%3};"
                 : "+f"(c[0]), "+f"(c[1]), "+f"(c[2]), "+f"(c[3])
                 : "r"(a[0]), "r"(a[1]), "r"(a[2]), "r"(a[3]), "r"(b[0]), "r"(b[1]));
}

template <bool BIAS, bool HOUT>
__global__ __launch_bounds__(256, 1) void k_mma_gemm(
    const __half* __restrict__ Ahi, const __half* __restrict__ Alo,
    const __half* __restrict__ Bh,
    const float* __restrict__ bias, float* __restrict__ C, __half* __restrict__ Ch,
    int M, int Nreal, int Nphys, int K) {
    extern __shared__ __half smem[];
    __half* sAh = smem;                       // 2 stages * BM*AP
    __half* sAl = sAh + 2 * BM * AP;
    __half* sBh = sAl + 2 * BM * AP;          // 2 stages * BK*BP

    int tid = threadIdx.x;
    int lane = tid & 31, wid = tid >> 5;
    int wm = (wid >> 2) * 64;
    int wn = (wid & 3) * 32;
    int bm = blockIdx.y * BM, bn = blockIdx.x * BN;

    float acc[4][4][4];
#pragma unroll
    for (int i = 0; i < 4; i++)
#pragma unroll
        for (int j = 0; j < 4; j++)
#pragma unroll
            for (int k = 0; k < 4; k++) acc[i][j][k] = 0.f;

    const int nk = K / BK;

    auto load_stage = [&](int st, int kt) {
        __half* ah = sAh + st * BM * AP;
        __half* al = sAl + st * BM * AP;
        __half* bh = sBh + st * BK * BP;
#pragma unroll
        for (int i = 0; i < 2; i++) {
            int q = tid + i * 256;           // 512 chunks: 128 rows x 4x16B
            int r = q >> 2, c = q & 3;
            size_t goff = (size_t)(bm + r) * K + kt * BK + c * 8;
            cp16(ah + r * AP + c * 8, Ahi + goff);
            cp16(al + r * AP + c * 8, Alo + goff);
        }
#pragma unroll
        for (int i = 0; i < 2; i++) {
            int q = tid + i * 256;           // 512 chunks: 32 rows x 16x16B
            int r = q >> 4, c = q & 15;
            size_t goff = (size_t)(kt * BK + r) * Nphys + bn + c * 8;
            cp16(bh + r * BP + c * 8, Bh + goff);
        }
        asm volatile("cp.async.commit_group;\n");
    };

    load_stage(0, 0);

    for (int kt = 0; kt < nk; kt++) {
        if (kt + 1 < nk) {
            load_stage((kt + 1) & 1, kt + 1);
            asm volatile("cp.async.wait_group 1;\n");
        } else {
            asm volatile("cp.async.wait_group 0;\n");
        }
        __syncthreads();

        int st = kt & 1;
        const __half* ah = sAh + st * BM * AP;
        const __half* al = sAl + st * BM * AP;
        const __half* bh = sBh + st * BK * BP;

#pragma unroll
        for (int ks = 0; ks < 2; ks++) {
            uint32_t Ah[4][4], Al[4][4], Bf[4][2];
            int arow = (lane & 15), ahalf = (lane >> 4);
#pragma unroll
            for (int mt = 0; mt < 4; mt++) {
                const __half* pa =
                    ah + (size_t)(wm + mt * 16 + arow) * AP + ks * 16 + ahalf * 8;
                const __half* pl =
                    al + (size_t)(wm + mt * 16 + arow) * AP + ks * 16 + ahalf * 8;
                ldmA(Ah[mt], pa);
                ldmA(Al[mt], pl);
            }
#pragma unroll
            for (int nt = 0; nt < 4; nt++) {
                const __half* pb =
                    bh + (size_t)(ks * 16 + (lane & 15)) * BP + wn + nt * 8;
                ldmB(Bf[nt], pb);
            }
#pragma unroll
            for (int mt = 0; mt < 4; mt++)
#pragma unroll
                for (int nt = 0; nt < 4; nt++) {
                    mma_fp16(acc[mt][nt], Ah[mt], Bf[nt]);
                    mma_fp16(acc[mt][nt], Al[mt], Bf[nt]);
                }
        }
        __syncthreads();
    }

#pragma unroll
    for (int mt = 0; mt < 4; mt++) {
#pragma unroll
        for (int nt = 0; nt < 4; nt++) {
#pragma unroll
            for (int i = 0; i < 4; i++) {
                int row = bm + wm + mt * 16 + (lane >> 2) + (i >> 1) * 8;
                int col = bn + wn + nt * 8 + (lane & 3) * 2 + (i & 1);
                if (row < M && col < Nreal) {
                    float v = acc[mt][nt][i];
                    if (BIAS) v += bias[col];
                    if (HOUT) Ch[(size_t)row * Nreal + col] = __float2half(v);
                    else      C[(size_t)row * Nreal + col] = v;
                }
            }
        }
    }
}

// ---------------------------------------------------------------------------
// CSR aggregation over F=400 fp16 features, one block (128 thr) per node.
// 100 lanes x uint2 (4 halves, LDG.64) per edge; fp32 accumulation.
// ---------------------------------------------------------------------------
template <bool RELU, bool HILO>
__global__ __launch_bounds__(128) void k_aggregate(
    const __half* __restrict__ H, const float* __restrict__ bias,
    __half* __restrict__ outH, __half* __restrict__ outHi,
    __half* __restrict__ outLo, int node0) {
    __shared__ int   s_idx[128];
    __shared__ float s_w[128];

    int node = blockIdx.x + node0;
    int tid = threadIdx.x;
    int start = g_rowptr[node], end = g_rowptr[node + 1];
    float dd = g_dinv[node];

    float4 acc = make_float4(0.f, 0.f, 0.f, 0.f);
    const bool active = tid < (F_HID / 4);   // 100 uint2 lanes

    for (int base = start; base < end; base += 128) {
        int cnt = min(128, end - base);
        if (tid < cnt) {
            int s = g_csr[base + tid];
            s_idx[tid] = s;
            s_w[tid] = g_dinv[s] * dd;
        }
        __syncthreads();
        if (active) {
            int j = 0;
            for (; j + 4 <= cnt; j += 4) {
                uint2 u0 = ((const uint2*)(H + (size_t)s_idx[j + 0] * F_HID))[tid];
                uint2 u1 = ((const uint2*)(H + (size_t)s_idx[j + 1] * F_HID))[tid];
                uint2 u2 = ((const uint2*)(H + (size_t)s_idx[j + 2] * F_HID))[tid];
                uint2 u3 = ((const uint2*)(H + (size_t)s_idx[j + 3] * F_HID))[tid];
                float w0 = s_w[j + 0], w1 = s_w[j + 1];
                float w2 = s_w[j + 2], w3 = s_w[j + 3];
                float2 a0 = __half22float2(*(__half2*)&u0.x);
                float2 b0 = __half22float2(*(__half2*)&u0.y);
                float2 a1 = __half22float2(*(__half2*)&u1.x);
                float2 b1 = __half22float2(*(__half2*)&u1.y);
                float2 a2 = __half22float2(*(__half2*)&u2.x);
                float2 b2 = __half22float2(*(__half2*)&u2.y);
                float2 a3 = __half22float2(*(__half2*)&u3.x);
                float2 b3 = __half22float2(*(__half2*)&u3.y);
                acc.x += a0.x * w0; acc.y += a0.y * w0;
                acc.z += b0.x * w0; acc.w += b0.y * w0;
                acc.x += a1.x * w1; acc.y += a1.y * w1;
                acc.z += b1.x * w1; acc.w += b1.y * w1;
                acc.x += a2.x * w2; acc.y += a2.y * w2;
                acc.z += b2.x * w2; acc.w += b2.y * w2;
                acc.x += a3.x * w3; acc.y += a3.y * w3;
                acc.z += b3.x * w3; acc.w += b3.y * w3;
            }
            for (; j < cnt; j++) {
                uint2 u0 = ((const uint2*)(H + (size_t)s_idx[j] * F_HID))[tid];
                float w0 = s_w[j];
                float2 a0 = __half22float2(*(__half2*)&u0.x);
                float2 b0 = __half22float2(*(__half2*)&u0.y);
                acc.x += a0.x * w0; acc.y += a0.y * w0;
                acc.z += b0.x * w0; acc.w += b0.y * w0;
            }
        }
        __syncthreads();
    }

    if (active) {
        if (bias) {
            float4 b = ((const float4*)bias)[tid];
            acc.x += b.x; acc.y += b.y; acc.z += b.z; acc.w += b.w;
        }
        if (RELU) {
            acc.x = fmaxf(acc.x, 0.f); acc.y = fmaxf(acc.y, 0.f);
            acc.z = fmaxf(acc.z, 0.f); acc.w = fmaxf(acc.w, 0.f);
        }
        if (HILO) {
            float v[4] = {acc.x, acc.y, acc.z, acc.w};
            __half hh[4], ll[4];
#pragma unroll
            for (int k = 0; k < 4; k++) split_fp16(v[k], hh[k], ll[k]);
            *(uint2*)(outHi + (size_t)node * K2P + tid * 4) = *(uint2*)hh;
            *(uint2*)(outLo + (size_t)node * K2P + tid * 4) = *(uint2*)ll;
        } else {
            __half2 h01 = __floats2half2_rn(acc.x, acc.y);
            __half2 h23 = __floats2half2_rn(acc.z, acc.w);
            uint2 u;
            u.x = *(uint32_t*)&h01; u.y = *(uint32_t*)&h23;
            ((uint2*)(outH + (size_t)node * F_HID))[tid] = u;
        }
    }
}

// ---------------------------------------------------------------------------
// launch
// ---------------------------------------------------------------------------
extern "C" void kernel_launch(void* const* d_in, const int* in_sizes, int n_in,
                              void* d_out, int out_size) {
    const float* x  = (const float*)d_in[0];
    const void*  ei = d_in[1];
    const float* W1 = (const float*)d_in[2];
    const float* b1 = (const float*)d_in[3];
    const float* W2 = (const float*)d_in[4];
    const float* b2 = (const float*)d_in[5];
    float* out = (float*)d_out;

    const int N = N_NODES;
    const int E = in_sizes[1] / 2;
    const int H2 = in_sizes[5];                       // 800

    __half *h1h, *agg1h, *xhi, *xlo, *a2hi, *a2lo, *w1h, *w2h;
    int *deg, *rowptr, *bsums;
    cudaGetSymbolAddress((void**)&h1h, g_h1h);
    cudaGetSymbolAddress((void**)&agg1h, g_agg1h);
    cudaGetSymbolAddress((void**)&xhi, g_xhi);
    cudaGetSymbolAddress((void**)&xlo, g_xlo);
    cudaGetSymbolAddress((void**)&a2hi, g_a2hi);
    cudaGetSymbolAddress((void**)&a2lo, g_a2lo);
    cudaGetSymbolAddress((void**)&w1h, g_w1h);
    cudaGetSymbolAddress((void**)&w2h, g_w2h);
    cudaGetSymbolAddress((void**)&deg, g_deg);
    cudaGetSymbolAddress((void**)&rowptr, g_rowptr);
    cudaGetSymbolAddress((void**)&bsums, g_bsums);

    static int inited = 0;
    static cudaStream_t s2;
    static cudaEvent_t evRoot, evCsr, evA, evG2;
    if (!inited) {
        cudaFuncSetAttribute(k_mma_gemm<false, true>,
                             cudaFuncAttributeMaxDynamicSharedMemorySize, GEMM_SMEM);
        cudaFuncSetAttribute(k_mma_gemm<true, false>,
                             cudaFuncAttributeMaxDynamicSharedMemorySize, GEMM_SMEM);
        cudaStreamCreateWithFlags(&s2, cudaStreamNonBlocking);
        cudaEventCreateWithFlags(&evRoot, cudaEventDisableTiming);
        cudaEventCreateWithFlags(&evCsr, cudaEventDisableTiming);
        cudaEventCreateWithFlags(&evA, cudaEventDisableTiming);
        cudaEventCreateWithFlags(&evG2, cudaEventDisableTiming);
        inited = 1;
    }

    // ---- fork ---------------------------------------------------------------
    cudaEventRecord(evRoot, 0);
    cudaStreamWaitEvent(s2, evRoot, 0);

    // main: conversions needed by GEMM1
    k_conv_x<<<(N * K1 + 255) / 256, 256>>>(x, N * K1);
    k_conv_w1<<<(K1 * N1P + 255) / 256, 256>>>(W1);

    // s2: W2 conversion + full CSR build chain (latency-bound, overlaps GEMM1)
    k_conv_w2<<<(K2P * N2P + 255) / 256, 256, 0, s2>>>(W2, H2);
    k_detect<<<1, 32, 0, s2>>>(ei);
    k_init<<<(N + 255) / 256, 256, 0, s2>>>(N);
    k_count_deg<<<(E + 255) / 256, 256, 0, s2>>>(ei, E);
    k_dinv<<<(N + 255) / 256, 256, 0, s2>>>(N);
    int nb = (N + 255) / 256;
    k_scan_blocks<<<nb, 256, 0, s2>>>(deg, rowptr, bsums, N);
    k_scan_sums<<<1, 256, 0, s2>>>(bsums, nb, rowptr + N);
    k_scan_add<<<nb, 256, 0, s2>>>(rowptr, bsums, N);
    k_fill_csr<<<(E + N + 255) / 256, 256, 0, s2>>>(ei, E, N);
    cudaEventRecord(evCsr, s2);

    // main: GEMM1 -> h1 (fp16)
    {
        dim3 grid(N1P / BN, (N + BM - 1) / BM);
        k_mma_gemm<false, true><<<grid, 256, GEMM_SMEM>>>(
            xhi, xlo, w1h, nullptr, nullptr, h1h, N, F_HID, N1P, K1);
    }

    // ---- join: aggregations need CSR ---------------------------------------
    cudaStreamWaitEvent(0, evCsr, 0);

    // agg1: fp16 gather -> fp16 out
    k_aggregate<true, false><<<N, 128>>>(h1h, b1, agg1h, nullptr, nullptr, 0);

    // agg2 chunk0 -> GEMM2 chunk0 on s2 (overlaps agg2 chunk1)
    k_aggregate<false, true><<<SPLIT_R, 128>>>(agg1h, nullptr, nullptr, a2hi, a2lo, 0);
    cudaEventRecord(evA, 0);
    cudaStreamWaitEvent(s2, evA, 0);
    {
        dim3 grid(N2P / BN, SPLIT_R / BM);
        k_mma_gemm<true, false><<<grid, 256, GEMM_SMEM, s2>>>(
            a2hi, a2lo, w2h, b2, out, nullptr, SPLIT_R, H2, N2P, K2P);
    }
    cudaEventRecord(evG2, s2);

    // main: agg2 chunk1, then GEMM2 chunk1
    k_aggregate<false, true><<<N - SPLIT_R, 128>>>(agg1h, nullptr, nullptr,
                                                   a2hi, a2lo, SPLIT_R);
    {
        int mrem = N - SPLIT_R;
        dim3 grid(N2P / BN, (mrem + BM - 1) / BM);
        k_mma_gemm<true, false><<<grid, 256, GEMM_SMEM>>>(
            a2hi + (size_t)SPLIT_R * K2P, a2lo + (size_t)SPLIT_R * K2P,
            w2h, b2, out + (size_t)SPLIT_R * H2, nullptr, mrem, H2, N2P, K2P);
    }
    cudaStreamWaitEvent(0, evG2, 0);
}